// round 12
// baseline (speedup 1.0000x reference)
#include <cuda_runtime.h>
#include <cuda_fp16.h>
#include <stdint.h>
#include <math.h>

#define EMBED 512
#define NBATCH 8
#define QLEN 2048
#define KLEN 4096
#define MQ (NBATCH*QLEN)
#define MK (NBATCH*KLEN)
#define NBLK (KLEN/128)

__device__ __half g_x16[MQ*EMBED];
__device__ __half g_y16[MK*EMBED];
__device__ __half g_W16[4][EMBED*EMBED];     // q,k,v,o (contiguous)
__device__ __half g_Q16[MQ*EMBED];
__device__ __half g_K16[MK*EMBED];
__device__ __half g_Vt16[(size_t)NBATCH*EMBED*KLEN];
__device__ __half g_E16[(size_t)MQ*KLEN];
__device__ __half g_O16[MQ*EMBED];
__device__ float  g_Esum[(size_t)MQ*NBLK];

__device__ __forceinline__ uint32_t smem_u32(const void* p){
    uint32_t a;
    asm("{ .reg .u64 t; cvta.to.shared.u64 t, %1; cvt.u32.u64 %0, t; }" : "=r"(a) : "l"(p));
    return a;
}
#define CP16(s,g)   asm volatile("cp.async.cg.shared.global [%0], [%1], 16;" :: "r"(s), "l"(g) : "memory")
#define CP_COMMIT() asm volatile("cp.async.commit_group;" ::: "memory")
#define CP_WAIT1()  asm volatile("cp.async.wait_group 1;" ::: "memory")
#define CP_WAIT0()  asm volatile("cp.async.wait_group 0;" ::: "memory")

__device__ __forceinline__ void ldm4(uint32_t* r, uint32_t a){
    asm volatile("ldmatrix.sync.aligned.m8n8.x4.shared.b16 {%0,%1,%2,%3}, [%4];"
        : "=r"(r[0]), "=r"(r[1]), "=r"(r[2]), "=r"(r[3]) : "r"(a));
}
__device__ __forceinline__ void mma_f16(float* c, const uint32_t* a, const uint32_t* b){
    asm volatile("mma.sync.aligned.m16n8k16.row.col.f32.f16.f16.f32 "
        "{%0,%1,%2,%3}, {%4,%5,%6,%7}, {%8,%9}, {%0,%1,%2,%3};"
        : "+f"(c[0]), "+f"(c[1]), "+f"(c[2]), "+f"(c[3])
        : "r"(a[0]), "r"(a[1]), "r"(a[2]), "r"(a[3]), "r"(b[0]), "r"(b[1]));
}
__device__ __forceinline__ void mma_h(uint32_t* c, const uint32_t* a, const uint32_t* b){
    asm volatile("mma.sync.aligned.m16n8k16.row.col.f16.f16.f16.f16 "
        "{%0,%1}, {%2,%3,%4,%5}, {%6,%7}, {%0,%1};"
        : "+r"(c[0]), "+r"(c[1])
        : "r"(a[0]), "r"(a[1]), "r"(a[2]), "r"(a[3]), "r"(b[0]), "r"(b[1]));
}

// ---------------- shared GEMM core: tile 128x128, k64 stage, 3-stage, 1 sync/stage ----------------
// D[m][n] = sum_k A[(m0+m)][k] * B[(n0+n)][k].  8 warps = 4(m) x 2(n); warp 32x64.
// HACC: fp16 accumulators + register-level frag double-buffering (EPI 3/4).
// EPI 0: fp16 out.                      EPI 1: transpose -> Vt[batch][n0c+d][kk].
// EPI 2: f32 = acc + resid + bias.      EPI 3: exp(scale*acc) fp16 + row partial sums.
// EPI 4: fp16 * (1/rowsum).
#define STAGE_B 32768
#define GSMEM   (3*STAGE_B + 1024)

template<int EPI, bool HACC>
__device__ __forceinline__ void gemm_core(
    const __half* __restrict__ A, int lda,
    const __half* __restrict__ B, int ldb, int Kdim,
    int m0, int n0, int n0c,
    __half* __restrict__ C16, int ldc,
    float* __restrict__ Cf, const float* __restrict__ resid,
    const float* __restrict__ bias, float scale,
    float* __restrict__ esBase, int nblk, char* dynsm)
{
    const uint32_t smbase = smem_u32(dynsm);
    const uint32_t tiles = (smbase + 1023u) & ~1023u;
    const int tid = threadIdx.x, lane = tid & 31, wid = tid >> 5;
    const int wm = wid & 3, wn = wid >> 2;

    float    accf[HACC ? 1 : 2][8][HACC ? 1 : 4];
    uint32_t acch[HACC ? 2 : 1][8][HACC ? 2 : 1];
    if (HACC){
        #pragma unroll
        for (int i = 0; i < 2; i++)
            #pragma unroll
            for (int j = 0; j < 8; j++){ acch[i][j][0] = 0u; acch[i][j][1] = 0u; }
    } else {
        #pragma unroll
        for (int i = 0; i < 2; i++)
            #pragma unroll
            for (int j = 0; j < 8; j++)
                #pragma unroll
                for (int k = 0; k < 4; k++) accf[i][j][k] = 0.f;
    }

    const int r_lane = (lane & 7) + ((lane >> 3) & 1) * 8;
    uint32_t aRow[2], aSw[2];
    #pragma unroll
    for (int mt = 0; mt < 2; mt++){
        int m_loc = wm * 32 + mt * 16 + r_lane;
        aRow[mt] = (uint32_t)(m_loc * 128);
        aSw[mt]  = (uint32_t)(m_loc & 7);
    }
    const uint32_t aCk = (lane >> 4) & 1;
    uint32_t bRow[4], bSw[4];
    {
        int n_base = wn * 64 + ((lane >> 4) & 1) * 8 + (lane & 7);
        #pragma unroll
        for (int g = 0; g < 4; g++){
            int n_loc = n_base + g * 16;
            bRow[g] = (uint32_t)(n_loc * 128);
            bSw[g]  = (uint32_t)(n_loc & 7);
        }
    }
    const uint32_t bCk = (lane >> 3) & 1;

    const int C = Kdim >> 6;

    auto load_stage = [&](int c){
        const uint32_t sb = tiles + (c % 3) * STAGE_B;
        const int k0 = c << 6;
        #pragma unroll
        for (int i = 0; i < 4; i++){
            int idx = tid + i * 256;
            int row = idx >> 3, ch = idx & 7;
            uint32_t so = (uint32_t)(row * 128 + ((ch ^ (row & 7)) << 4));
            CP16(sb + so, A + (size_t)(m0 + row) * lda + k0 + ch * 8);
        }
        #pragma unroll
        for (int i = 0; i < 4; i++){
            int idx = tid + i * 256;
            int row = idx >> 3, ch = idx & 7;
            uint32_t so = (uint32_t)(row * 128 + ((ch ^ (row & 7)) << 4));
            CP16(sb + 16384 + so, B + (size_t)(n0 + row) * ldb + k0 + ch * 8);
        }
    };

    // load A frags (2 ldm4) + B frags (4 ldm4 -> 8 n-frags) for one ks
    auto load_frags = [&](uint32_t sb, int ks, uint32_t ahd[2][4], uint32_t bbd[8][2]){
        #pragma unroll
        for (int mt = 0; mt < 2; mt++){
            uint32_t off = aRow[mt] + ((((uint32_t)(2 * ks) + aCk) ^ aSw[mt]) << 4);
            ldm4(ahd[mt], sb + off);
        }
        #pragma unroll
        for (int g = 0; g < 4; g++){
            uint32_t off = bRow[g] + ((((uint32_t)(2 * ks) + bCk) ^ bSw[g]) << 4);
            uint32_t q[4];
            ldm4(q, sb + 16384 + off);
            bbd[2*g][0]=q[0]; bbd[2*g][1]=q[1]; bbd[2*g+1][0]=q[2]; bbd[2*g+1][1]=q[3];
        }
    };

    load_stage(0); CP_COMMIT();
    load_stage(1); CP_COMMIT();

    if (HACC){
        // register-pipelined mainloop: double-buffered frags, fp16 accum
        uint32_t ah[2][2][4], bb[2][8][2];
        for (int c = 0; c < C; c++){
            if (c < C - 1) CP_WAIT1(); else CP_WAIT0();
            __syncthreads();
            if (c + 2 < C){ load_stage(c + 2); CP_COMMIT(); }

            const uint32_t sb = tiles + (c % 3) * STAGE_B;
            load_frags(sb, 0, ah[0], bb[0]);
            #pragma unroll
            for (int ks = 0; ks < 4; ks++){
                const int cur = ks & 1, nxt = cur ^ 1;
                if (ks < 3) load_frags(sb, ks + 1, ah[nxt], bb[nxt]);
                #pragma unroll
                for (int mt = 0; mt < 2; mt++)
                    #pragma unroll
                    for (int nf = 0; nf < 8; nf++)
                        mma_h(acch[mt][nf], ah[cur][mt], bb[cur][nf]);
            }
        }
    } else {
        for (int c = 0; c < C; c++){
            if (c < C - 1) CP_WAIT1(); else CP_WAIT0();
            __syncthreads();
            if (c + 2 < C){ load_stage(c + 2); CP_COMMIT(); }

            const uint32_t sb = tiles + (c % 3) * STAGE_B;
            #pragma unroll
            for (int ks = 0; ks < 4; ks++){
                uint32_t ah[2][4], bb[8][2];
                load_frags(sb, ks, ah, bb);
                #pragma unroll
                for (int mt = 0; mt < 2; mt++)
                    #pragma unroll
                    for (int nf = 0; nf < 8; nf++)
                        mma_f16(accf[mt][nf], ah[mt], bb[nf]);
            }
        }
    }

    const int er = lane >> 2, ec = (lane & 3) * 2;
    if (EPI == 1){
        __half* s = reinterpret_cast<__half*>(dynsm + (tiles - smbase));
        __syncthreads();
        #pragma unroll
        for (int mt = 0; mt < 2; mt++)
            #pragma unroll
            for (int nf = 0; nf < 8; nf++){
                const int dn = wn * 64 + nf * 8 + ec;
                #pragma unroll
                for (int rr = 0; rr < 2; rr++){
                    const int km = wm * 32 + mt * 16 + er + rr * 8;
                    s[(size_t)dn * 136 + km]     = __float2half(accf[mt][nf][rr*2]);
                    s[(size_t)(dn+1) * 136 + km] = __float2half(accf[mt][nf][rr*2+1]);
                }
            }
        __syncthreads();
        const int batch = m0 / KLEN;
        const int kkb   = m0 % KLEN;
        #pragma unroll
        for (int pass = 0; pass < 8; pass++){
            int drow = (tid >> 4) + pass * 16;
            int seg  = tid & 15;
            uint4 v = *reinterpret_cast<const uint4*>(s + (size_t)drow * 136 + seg * 8);
            *reinterpret_cast<uint4*>(C16 + ((size_t)batch * EMBED + n0c + drow) * KLEN + kkb + seg * 8) = v;
        }
        return;
    }
    if (EPI == 3){
        float* rs = reinterpret_cast<float*>(dynsm + (tiles - smbase));
        float rowp[2][2] = {};
        #pragma unroll
        for (int mt = 0; mt < 2; mt++)
            #pragma unroll
            for (int nf = 0; nf < 8; nf++){
                const int n = n0c + wn * 64 + nf * 8 + ec;
                #pragma unroll
                for (int rr = 0; rr < 2; rr++){
                    const int m = m0 + wm * 32 + mt * 16 + er + rr * 8;
                    __half2 hv = *reinterpret_cast<__half2*>(&acch[mt][nf][rr]);
                    float e0 = __expf(__low2float(hv)  * scale);
                    float e1 = __expf(__high2float(hv) * scale);
                    __half2 hp = __floats2half2_rn(e0, e1);
                    *reinterpret_cast<uint32_t*>(C16 + (size_t)m * ldc + n) = *reinterpret_cast<uint32_t*>(&hp);
                    rowp[mt][rr] += e0 + e1;
                }
            }
        __syncthreads();
        #pragma unroll
        for (int mt = 0; mt < 2; mt++)
            #pragma unroll
            for (int rr = 0; rr < 2; rr++){
                float v = rowp[mt][rr];
                v += __shfl_xor_sync(0xffffffffu, v, 1);
                v += __shfl_xor_sync(0xffffffffu, v, 2);
                if ((lane & 3) == 0){
                    int row = wm * 32 + mt * 16 + rr * 8 + er;
                    rs[wn * 128 + row] = v;
                }
            }
        __syncthreads();
        if (tid < 128)
            esBase[(size_t)(m0 + tid) * NBLK + nblk] = rs[tid] + rs[128 + tid];
        return;
    }
    if (EPI == 4){
        float invr[2][2];
        #pragma unroll
        for (int mt = 0; mt < 2; mt++)
            #pragma unroll
            for (int rr = 0; rr < 2; rr++){
                const int m = m0 + wm * 32 + mt * 16 + er + rr * 8;
                const float4* p = reinterpret_cast<const float4*>(esBase + (size_t)m * NBLK);
                float s = 0.f;
                #pragma unroll
                for (int i = 0; i < NBLK/4; i++){
                    float4 v = p[i];
                    s += (v.x + v.y) + (v.z + v.w);
                }
                invr[mt][rr] = 1.f / s;
            }
        #pragma unroll
        for (int mt = 0; mt < 2; mt++)
            #pragma unroll
            for (int nf = 0; nf < 8; nf++){
                const int n = n0c + wn * 64 + nf * 8 + ec;
                #pragma unroll
                for (int rr = 0; rr < 2; rr++){
                    const int m = m0 + wm * 32 + mt * 16 + er + rr * 8;
                    __half2 hv = *reinterpret_cast<__half2*>(&acch[mt][nf][rr]);
                    __half2 hp = __floats2half2_rn(__low2float(hv)  * invr[mt][rr],
                                                   __high2float(hv) * invr[mt][rr]);
                    *reinterpret_cast<uint32_t*>(C16 + (size_t)m * ldc + n) = *reinterpret_cast<uint32_t*>(&hp);
                }
            }
        return;
    }
    #pragma unroll
    for (int mt = 0; mt < 2; mt++)
        #pragma unroll
        for (int nf = 0; nf < 8; nf++){
            const int n = n0c + wn * 64 + nf * 8 + ec;
            #pragma unroll
            for (int rr = 0; rr < 2; rr++){
                const int m = m0 + wm * 32 + mt * 16 + er + rr * 8;
                float v0 = accf[mt][nf][rr * 2], v1 = accf[mt][nf][rr * 2 + 1];
                if (EPI == 0){
                    __half2 hp = __floats2half2_rn(v0, v1);
                    *reinterpret_cast<uint32_t*>(C16 + (size_t)m * ldc + n) = *reinterpret_cast<uint32_t*>(&hp);
                } else {
                    size_t off = (size_t)m * ldc + n;
                    float2 rv = *reinterpret_cast<const float2*>(resid + off);
                    float2 bv = *reinterpret_cast<const float2*>(bias + n);
                    float2 o; o.x = v0 + rv.x + bv.x; o.y = v1 + rv.y + bv.y;
                    *reinterpret_cast<float2*>(Cf + off) = o;
                }
            }
        }
}

// ---------------- fused QKV projection: Q (512 blocks) + KV (2048 blocks) ----------------
__global__ void __launch_bounds__(256, 2)
qkvproj(const __half* __restrict__ x16, const __half* __restrict__ y16,
        const __half* __restrict__ W16,
        __half* __restrict__ Q16, __half* __restrict__ K16, __half* __restrict__ Vt16)
{
    extern __shared__ char dynsm[];
    int id = blockIdx.x;
    const __half* A; const __half* B; __half* C;
    int m0, n0, n0c; bool isV = false;
    if (id < 512){
        m0 = (id >> 2) * 128; n0 = (id & 3) * 128; n0c = n0;
        A = x16; B = W16; C = Q16;                      // Wq
    } else {
        id -= 512;
        m0 = (id >> 3) * 128; n0 = (id & 7) * 128;
        A = y16; B = W16 + (size_t)EMBED * EMBED;       // [Wk;Wv]
        if (n0 < 512){ n0c = n0; C = K16; }
        else { n0c = n0 - 512; C = Vt16; isV = true; }
    }
    if (!isV)
        gemm_core<0,false>(A, EMBED, B, EMBED, EMBED, m0, n0, n0c, C, EMBED,
                     nullptr, nullptr, nullptr, 1.0f, nullptr, 0, dynsm);
    else
        gemm_core<1,false>(A, EMBED, B, EMBED, EMBED, m0, n0, n0c, C, 0,
                     nullptr, nullptr, nullptr, 1.0f, nullptr, 0, dynsm);
}

// ---------------- E = exp(sc * Q K^T) + partial sums (f16 accum, pipelined) ----------------
__global__ void __launch_bounds__(256, 2)
gemmE(const __half* __restrict__ Q16, const __half* __restrict__ K16,
      __half* __restrict__ E16, float* __restrict__ Esum, float scale)
{
    extern __shared__ char dynsm[];
    const int b = blockIdx.z;
    gemm_core<3,true>(Q16 + (size_t)b * QLEN * EMBED, EMBED,
                 K16 + (size_t)b * KLEN * EMBED, EMBED, EMBED,
                 blockIdx.y * 128, blockIdx.x * 128, blockIdx.x * 128,
                 E16 + (size_t)b * QLEN * KLEN, KLEN,
                 nullptr, nullptr, nullptr, scale,
                 Esum + (size_t)b * QLEN * NBLK, blockIdx.x, dynsm);
}

// ---------------- O = (E @ Vt^T) / rowsum (f16 accum, pipelined) ----------------
__global__ void __launch_bounds__(256, 2)
gemmAV(const __half* __restrict__ E16, const __half* __restrict__ Vt16,
       __half* __restrict__ O16, const float* __restrict__ Esum)
{
    extern __shared__ char dynsm[];
    const int b = blockIdx.z;
    gemm_core<4,true>(E16 + (size_t)b * QLEN * KLEN, KLEN,
                 Vt16 + (size_t)b * EMBED * KLEN, KLEN, KLEN,
                 blockIdx.y * 128, blockIdx.x * 128, blockIdx.x * 128,
                 O16 + (size_t)b * QLEN * EMBED, EMBED,
                 nullptr, nullptr, nullptr, 1.0f,
                 const_cast<float*>(Esum) + (size_t)b * QLEN * NBLK, 0, dynsm);
}

// ---------------- out = x + O @ Wo^T + bo ----------------
__global__ void __launch_bounds__(256, 2)
gemmOut(const __half* __restrict__ O16, const __half* __restrict__ W16,
        float* __restrict__ out, const float* __restrict__ x, const float* __restrict__ bo)
{
    extern __shared__ char dynsm[];
    gemm_core<2,false>(O16, EMBED, W16 + (size_t)3 * EMBED * EMBED, EMBED, EMBED,
                 blockIdx.y * 128, blockIdx.x * 128, blockIdx.x * 128,
                 nullptr, EMBED, out, x, bo, 1.0f, nullptr, 0, dynsm);
}

// ---------------- one convert kernel for x, y, Wq..Wo ----------------
#define NX (MQ*EMBED)
#define NY (MK*EMBED)
#define NW (EMBED*EMBED)
__global__ void __launch_bounds__(256, 1)
cvtAll(const float* __restrict__ x, const float* __restrict__ y,
       const float* __restrict__ w0, const float* __restrict__ w1,
       const float* __restrict__ w2, const float* __restrict__ w3,
       __half* __restrict__ x16, __half* __restrict__ y16, __half* __restrict__ W16)
{
    int e = (blockIdx.x * 256 + threadIdx.x) * 4;
    const float* src; __half* dst;
    if (e < NX){ src = x + e; dst = x16 + e; }
    else if (e < NX + NY){ int o = e - NX; src = y + o; dst = y16 + o; }
    else {
        int o = e - NX - NY;
        int w = o / NW, r = o % NW;
        src = (w == 0 ? w0 : w == 1 ? w1 : w == 2 ? w2 : w3) + r;
        dst = W16 + (size_t)w * NW + r;
    }
    float4 v = *reinterpret_cast<const float4*>(src);
    __half2 a = __floats2half2_rn(v.x, v.y);
    __half2 b = __floats2half2_rn(v.z, v.w);
    uint2 o;
    o.x = *reinterpret_cast<uint32_t*>(&a);
    o.y = *reinterpret_cast<uint32_t*>(&b);
    *reinterpret_cast<uint2*>(dst) = o;
}

// ---------------- launch ----------------
extern "C" void kernel_launch(void* const* d_in, const int* in_sizes, int n_in,
                              void* d_out, int out_size)
{
    const float* x  = (const float*)d_in[0];
    const float* y  = (const float*)d_in[1];
    const float* Wq = (const float*)d_in[2];
    const float* Wk = (const float*)d_in[3];
    const float* Wv = (const float*)d_in[4];
    const float* Wo = (const float*)d_in[5];
    const float* bo = (const float*)d_in[6];
    float* out = (float*)d_out;

    __half *x16,*y16,*W16,*Q16,*K16,*Vt16,*E16,*O16;
    float *Esum;
    cudaGetSymbolAddress((void**)&x16,  g_x16);
    cudaGetSymbolAddress((void**)&y16,  g_y16);
    cudaGetSymbolAddress((void**)&W16,  g_W16);
    cudaGetSymbolAddress((void**)&Q16,  g_Q16);
    cudaGetSymbolAddress((void**)&K16,  g_K16);
    cudaGetSymbolAddress((void**)&Vt16, g_Vt16);
    cudaGetSymbolAddress((void**)&E16,  g_E16);
    cudaGetSymbolAddress((void**)&O16,  g_O16);
    cudaGetSymbolAddress((void**)&Esum, g_Esum);
    cudaFuncSetAttribute(qkvproj, cudaFuncAttributeMaxDynamicSharedMemorySize, GSMEM);
    cudaFuncSetAttribute(gemmE,   cudaFuncAttributeMaxDynamicSharedMemorySize, GSMEM);
    cudaFuncSetAttribute(gemmAV,  cudaFuncAttributeMaxDynamicSharedMemorySize, GSMEM);
    cudaFuncSetAttribute(gemmOut, cudaFuncAttributeMaxDynamicSharedMemorySize, GSMEM);

    const float sc = 1.0f / sqrtf((float)EMBED);

    cvtAll<<<(NX + NY + 4*NW)/1024, 256>>>(x, y, Wq, Wk, Wv, Wo, x16, y16, W16);
    qkvproj<<<2560, 256, GSMEM>>>(x16, y16, W16, Q16, K16, Vt16);
    gemmE<<<dim3(KLEN/128, QLEN/128, NBATCH), 256, GSMEM>>>(Q16, K16, E16, Esum, sc);
    gemmAV<<<dim3(EMBED/128, QLEN/128, NBATCH), 256, GSMEM>>>(E16, Vt16, O16, Esum);
    gemmOut<<<dim3(EMBED/128, MQ/128, 1), 256, GSMEM>>>(O16, W16, out, x, bo);
}

// round 13
// speedup vs baseline: 1.0687x; 1.0687x over previous
#include <cuda_runtime.h>
#include <cuda_fp16.h>
#include <stdint.h>
#include <math.h>

#define EMBED 512
#define NBATCH 8
#define QLEN 2048
#define KLEN 4096
#define MQ (NBATCH*QLEN)
#define MK (NBATCH*KLEN)
#define NBLK (KLEN/128)

__device__ __half g_x16[MQ*EMBED];
__device__ __half g_y16[MK*EMBED];
__device__ __half g_W16[4][EMBED*EMBED];     // q,k,v(->Wvo),o (contiguous)
__device__ __half g_WvT16[EMBED*EMBED];
__device__ __half g_Q16[MQ*EMBED];
__device__ __half g_K16[MK*EMBED];
__device__ __half g_Vt16[(size_t)NBATCH*EMBED*KLEN];   // holds (y@Wvo^T)^T per batch
__device__ __half g_E16[(size_t)MQ*KLEN];
__device__ float  g_Esum[(size_t)MQ*NBLK];

__device__ __forceinline__ uint32_t smem_u32(const void* p){
    uint32_t a;
    asm("{ .reg .u64 t; cvta.to.shared.u64 t, %1; cvt.u32.u64 %0, t; }" : "=r"(a) : "l"(p));
    return a;
}
#define CP16(s,g)   asm volatile("cp.async.cg.shared.global [%0], [%1], 16;" :: "r"(s), "l"(g) : "memory")
#define CP_COMMIT() asm volatile("cp.async.commit_group;" ::: "memory")
#define CP_WAIT1()  asm volatile("cp.async.wait_group 1;" ::: "memory")
#define CP_WAIT0()  asm volatile("cp.async.wait_group 0;" ::: "memory")

__device__ __forceinline__ void ldm4(uint32_t* r, uint32_t a){
    asm volatile("ldmatrix.sync.aligned.m8n8.x4.shared.b16 {%0,%1,%2,%3}, [%4];"
        : "=r"(r[0]), "=r"(r[1]), "=r"(r[2]), "=r"(r[3]) : "r"(a));
}
__device__ __forceinline__ void mma_f16(float* c, const uint32_t* a, const uint32_t* b){
    asm volatile("mma.sync.aligned.m16n8k16.row.col.f32.f16.f16.f32 "
        "{%0,%1,%2,%3}, {%4,%5,%6,%7}, {%8,%9}, {%0,%1,%2,%3};"
        : "+f"(c[0]), "+f"(c[1]), "+f"(c[2]), "+f"(c[3])
        : "r"(a[0]), "r"(a[1]), "r"(a[2]), "r"(a[3]), "r"(b[0]), "r"(b[1]));
}

// ---------------- shared GEMM core (R10 config): tile 128x128, k64 stage, 3-stage, 1 sync ----------------
// D[m][n] = sum_k A[(m0+m)][k] * B[(n0+n)][k].  8 warps = 4(m) x 2(n); warp 32x64. f32 accum.
// EPI 0: fp16 out.   EPI 1: transpose -> Vt[batch][n0c+d][kk].
// EPI 3: exp(scale*acc) fp16 + row partial sums.
// EPI 5: f32 out = acc*(1/rowsum) + resid + bias   (final attention output, fused).
#define STAGE_B 32768
#define GSMEM   (3*STAGE_B + 1024)

template<int EPI>
__device__ __forceinline__ void gemm_core(
    const __half* __restrict__ A, int lda,
    const __half* __restrict__ B, int ldb, int Kdim,
    int m0, int n0, int n0c,
    __half* __restrict__ C16, int ldc,
    float* __restrict__ Cf, const float* __restrict__ resid,
    const float* __restrict__ bias, float scale,
    float* __restrict__ esBase, int nblk, char* dynsm)
{
    const uint32_t smbase = smem_u32(dynsm);
    const uint32_t tiles = (smbase + 1023u) & ~1023u;
    const int tid = threadIdx.x, lane = tid & 31, wid = tid >> 5;
    const int wm = wid & 3, wn = wid >> 2;

    float acc[2][8][4];
    #pragma unroll
    for (int i = 0; i < 2; i++)
        #pragma unroll
        for (int j = 0; j < 8; j++)
            #pragma unroll
            for (int k = 0; k < 4; k++) acc[i][j][k] = 0.f;

    const int r_lane = (lane & 7) + ((lane >> 3) & 1) * 8;
    uint32_t aRow[2], aSw[2];
    #pragma unroll
    for (int mt = 0; mt < 2; mt++){
        int m_loc = wm * 32 + mt * 16 + r_lane;
        aRow[mt] = (uint32_t)(m_loc * 128);
        aSw[mt]  = (uint32_t)(m_loc & 7);
    }
    const uint32_t aCk = (lane >> 4) & 1;
    uint32_t bRow[4], bSw[4];
    {
        int n_base = wn * 64 + ((lane >> 4) & 1) * 8 + (lane & 7);
        #pragma unroll
        for (int g = 0; g < 4; g++){
            int n_loc = n_base + g * 16;
            bRow[g] = (uint32_t)(n_loc * 128);
            bSw[g]  = (uint32_t)(n_loc & 7);
        }
    }
    const uint32_t bCk = (lane >> 3) & 1;

    const int C = Kdim >> 6;

    auto load_stage = [&](int c){
        const uint32_t sb = tiles + (c % 3) * STAGE_B;
        const int k0 = c << 6;
        #pragma unroll
        for (int i = 0; i < 4; i++){
            int idx = tid + i * 256;
            int row = idx >> 3, ch = idx & 7;
            uint32_t so = (uint32_t)(row * 128 + ((ch ^ (row & 7)) << 4));
            CP16(sb + so, A + (size_t)(m0 + row) * lda + k0 + ch * 8);
        }
        #pragma unroll
        for (int i = 0; i < 4; i++){
            int idx = tid + i * 256;
            int row = idx >> 3, ch = idx & 7;
            uint32_t so = (uint32_t)(row * 128 + ((ch ^ (row & 7)) << 4));
            CP16(sb + 16384 + so, B + (size_t)(n0 + row) * ldb + k0 + ch * 8);
        }
    };

    load_stage(0); CP_COMMIT();
    load_stage(1); CP_COMMIT();

    for (int c = 0; c < C; c++){
        if (c < C - 1) CP_WAIT1(); else CP_WAIT0();
        __syncthreads();
        if (c + 2 < C){ load_stage(c + 2); CP_COMMIT(); }

        const uint32_t sb = tiles + (c % 3) * STAGE_B;
        #pragma unroll
        for (int ks = 0; ks < 4; ks++){
            uint32_t ah[2][4];
            #pragma unroll
            for (int mt = 0; mt < 2; mt++){
                uint32_t off = aRow[mt] + ((((uint32_t)(2 * ks) + aCk) ^ aSw[mt]) << 4);
                ldm4(ah[mt], sb + off);
            }
            uint32_t bb[8][2];
            #pragma unroll
            for (int g = 0; g < 4; g++){
                uint32_t off = bRow[g] + ((((uint32_t)(2 * ks) + bCk) ^ bSw[g]) << 4);
                uint32_t q[4];
                ldm4(q, sb + 16384 + off);
                bb[2*g][0]=q[0]; bb[2*g][1]=q[1]; bb[2*g+1][0]=q[2]; bb[2*g+1][1]=q[3];
            }
            #pragma unroll
            for (int mt = 0; mt < 2; mt++)
                #pragma unroll
                for (int nf = 0; nf < 8; nf++)
                    mma_f16(acc[mt][nf], ah[mt], bb[nf]);
        }
    }

    const int er = lane >> 2, ec = (lane & 3) * 2;
    if (EPI == 1){
        __half* s = reinterpret_cast<__half*>(dynsm + (tiles - smbase));
        __syncthreads();
        #pragma unroll
        for (int mt = 0; mt < 2; mt++)
            #pragma unroll
            for (int nf = 0; nf < 8; nf++){
                const int dn = wn * 64 + nf * 8 + ec;
                #pragma unroll
                for (int rr = 0; rr < 2; rr++){
                    const int km = wm * 32 + mt * 16 + er + rr * 8;
                    s[(size_t)dn * 136 + km]     = __float2half(acc[mt][nf][rr*2]);
                    s[(size_t)(dn+1) * 136 + km] = __float2half(acc[mt][nf][rr*2+1]);
                }
            }
        __syncthreads();
        const int batch = m0 / KLEN;
        const int kkb   = m0 % KLEN;
        #pragma unroll
        for (int pass = 0; pass < 8; pass++){
            int drow = (tid >> 4) + pass * 16;
            int seg  = tid & 15;
            uint4 v = *reinterpret_cast<const uint4*>(s + (size_t)drow * 136 + seg * 8);
            *reinterpret_cast<uint4*>(C16 + ((size_t)batch * EMBED + n0c + drow) * KLEN + kkb + seg * 8) = v;
        }
        return;
    }
    if (EPI == 3){
        float* rs = reinterpret_cast<float*>(dynsm + (tiles - smbase));
        float rowp[2][2] = {};
        #pragma unroll
        for (int mt = 0; mt < 2; mt++)
            #pragma unroll
            for (int nf = 0; nf < 8; nf++){
                const int n = n0c + wn * 64 + nf * 8 + ec;
                #pragma unroll
                for (int rr = 0; rr < 2; rr++){
                    const int m = m0 + wm * 32 + mt * 16 + er + rr * 8;
                    float e0 = __expf(acc[mt][nf][rr*2]   * scale);
                    float e1 = __expf(acc[mt][nf][rr*2+1] * scale);
                    __half2 hp = __floats2half2_rn(e0, e1);
                    *reinterpret_cast<uint32_t*>(C16 + (size_t)m * ldc + n) = *reinterpret_cast<uint32_t*>(&hp);
                    rowp[mt][rr] += e0 + e1;
                }
            }
        __syncthreads();
        #pragma unroll
        for (int mt = 0; mt < 2; mt++)
            #pragma unroll
            for (int rr = 0; rr < 2; rr++){
                float v = rowp[mt][rr];
                v += __shfl_xor_sync(0xffffffffu, v, 1);
                v += __shfl_xor_sync(0xffffffffu, v, 2);
                if ((lane & 3) == 0){
                    int row = wm * 32 + mt * 16 + rr * 8 + er;
                    rs[wn * 128 + row] = v;
                }
            }
        __syncthreads();
        if (tid < 128)
            esBase[(size_t)(m0 + tid) * NBLK + nblk] = rs[tid] + rs[128 + tid];
        return;
    }
    if (EPI == 5){
        // final fused output: acc * (1/rowsum) + resid + bias
        float invr[2][2];
        #pragma unroll
        for (int mt = 0; mt < 2; mt++)
            #pragma unroll
            for (int rr = 0; rr < 2; rr++){
                const int m = m0 + wm * 32 + mt * 16 + er + rr * 8;
                const float4* p = reinterpret_cast<const float4*>(esBase + (size_t)m * NBLK);
                float s = 0.f;
                #pragma unroll
                for (int i = 0; i < NBLK/4; i++){
                    float4 v = p[i];
                    s += (v.x + v.y) + (v.z + v.w);
                }
                invr[mt][rr] = 1.f / s;
            }
        #pragma unroll
        for (int mt = 0; mt < 2; mt++)
            #pragma unroll
            for (int nf = 0; nf < 8; nf++){
                const int n = n0c + wn * 64 + nf * 8 + ec;
                #pragma unroll
                for (int rr = 0; rr < 2; rr++){
                    const int m = m0 + wm * 32 + mt * 16 + er + rr * 8;
                    size_t off = (size_t)m * ldc + n;
                    float2 rv = *reinterpret_cast<const float2*>(resid + off);
                    float2 bv = *reinterpret_cast<const float2*>(bias + n);
                    float2 o;
                    o.x = acc[mt][nf][rr*2]   * invr[mt][rr] + rv.x + bv.x;
                    o.y = acc[mt][nf][rr*2+1] * invr[mt][rr] + rv.y + bv.y;
                    *reinterpret_cast<float2*>(Cf + off) = o;
                }
            }
        return;
    }
    // EPI 0
    #pragma unroll
    for (int mt = 0; mt < 2; mt++)
        #pragma unroll
        for (int nf = 0; nf < 8; nf++){
            const int n = n0c + wn * 64 + nf * 8 + ec;
            #pragma unroll
            for (int rr = 0; rr < 2; rr++){
                const int m = m0 + wm * 32 + mt * 16 + er + rr * 8;
                __half2 hp = __floats2half2_rn(acc[mt][nf][rr*2], acc[mt][nf][rr*2+1]);
                *reinterpret_cast<uint32_t*>(C16 + (size_t)m * ldc + n) = *reinterpret_cast<uint32_t*>(&hp);
            }
        }
}

// ---------------- fused QKV projection: Q (512 blocks) + K/Wvo (2048 blocks) ----------------
__global__ void __launch_bounds__(256, 2)
qkvproj(const __half* __restrict__ x16, const __half* __restrict__ y16,
        const __half* __restrict__ W16,
        __half* __restrict__ Q16, __half* __restrict__ K16, __half* __restrict__ Vt16)
{
    extern __shared__ char dynsm[];
    int id = blockIdx.x;
    const __half* A; const __half* B; __half* C;
    int m0, n0, n0c; bool isV = false;
    if (id < 512){
        m0 = (id >> 2) * 128; n0 = (id & 3) * 128; n0c = n0;
        A = x16; B = W16; C = Q16;                      // Wq
    } else {
        id -= 512;
        m0 = (id >> 3) * 128; n0 = (id & 7) * 128;
        A = y16; B = W16 + (size_t)EMBED * EMBED;       // [Wk; Wvo]
        if (n0 < 512){ n0c = n0; C = K16; }
        else { n0c = n0 - 512; C = Vt16; isV = true; }
    }
    if (!isV)
        gemm_core<0>(A, EMBED, B, EMBED, EMBED, m0, n0, n0c, C, EMBED,
                     nullptr, nullptr, nullptr, 1.0f, nullptr, 0, dynsm);
    else
        gemm_core<1>(A, EMBED, B, EMBED, EMBED, m0, n0, n0c, C, 0,
                     nullptr, nullptr, nullptr, 1.0f, nullptr, 0, dynsm);
}

// ---------------- E = exp(sc * Q K^T) + partial sums ----------------
__global__ void __launch_bounds__(256, 2)
gemmE(const __half* __restrict__ Q16, const __half* __restrict__ K16,
      __half* __restrict__ E16, float* __restrict__ Esum, float scale)
{
    extern __shared__ char dynsm[];
    const int b = blockIdx.z;
    gemm_core<3>(Q16 + (size_t)b * QLEN * EMBED, EMBED,
                 K16 + (size_t)b * KLEN * EMBED, EMBED, EMBED,
                 blockIdx.y * 128, blockIdx.x * 128, blockIdx.x * 128,
                 E16 + (size_t)b * QLEN * KLEN, KLEN,
                 nullptr, nullptr, nullptr, scale,
                 Esum + (size_t)b * QLEN * NBLK, blockIdx.x, dynsm);
}

// ---------------- out = x + (E @ VOt^T)/rowsum + bo  (final, fused) ----------------
__global__ void __launch_bounds__(256, 2)
gemmAV(const __half* __restrict__ E16, const __half* __restrict__ Vt16,
       float* __restrict__ out, const float* __restrict__ x, const float* __restrict__ bo,
       const float* __restrict__ Esum)
{
    extern __shared__ char dynsm[];
    const int b = blockIdx.z;
    gemm_core<5>(E16 + (size_t)b * QLEN * KLEN, KLEN,
                 Vt16 + (size_t)b * EMBED * KLEN, KLEN, KLEN,
                 blockIdx.y * 128, blockIdx.x * 128, blockIdx.x * 128,
                 nullptr, EMBED,
                 out + (size_t)b * QLEN * EMBED, x + (size_t)b * QLEN * EMBED, bo, 1.0f,
                 const_cast<float*>(Esum) + (size_t)b * QLEN * NBLK, 0, dynsm);
}

// ---------------- Wvo = Wo @ Wv  (via WvT), fp16 out into W16[2] ----------------
__global__ void __launch_bounds__(256, 2)
gemmW(const __half* __restrict__ Wo16, const __half* __restrict__ WvT16,
      __half* __restrict__ Wvo16)
{
    extern __shared__ char dynsm[];
    gemm_core<0>(Wo16, EMBED, WvT16, EMBED, EMBED,
                 blockIdx.y * 128, blockIdx.x * 128, blockIdx.x * 128,
                 Wvo16, EMBED, nullptr, nullptr, nullptr, 1.0f, nullptr, 0, dynsm);
}

// ---------------- transpose Wv16 -> WvT16 (512x512) ----------------
__global__ void __launch_bounds__(256, 1)
trW(const __half* __restrict__ src, __half* __restrict__ dst)
{
    __shared__ __half s[32][33];
    const int x0 = blockIdx.x * 32, y0 = blockIdx.y * 32;
    const int tx = threadIdx.x & 31, ty = threadIdx.x >> 5;
    #pragma unroll
    for (int i = ty; i < 32; i += 8)
        s[i][tx] = src[(size_t)(y0 + i) * EMBED + x0 + tx];
    __syncthreads();
    #pragma unroll
    for (int i = ty; i < 32; i += 8)
        dst[(size_t)(x0 + i) * EMBED + y0 + tx] = s[tx][i];
}

// ---------------- one convert kernel for x, y, Wq..Wo ----------------
#define NX (MQ*EMBED)
#define NY (MK*EMBED)
#define NW (EMBED*EMBED)
__global__ void __launch_bounds__(256, 1)
cvtAll(const float* __restrict__ x, const float* __restrict__ y,
       const float* __restrict__ w0, const float* __restrict__ w1,
       const float* __restrict__ w2, const float* __restrict__ w3,
       __half* __restrict__ x16, __half* __restrict__ y16, __half* __restrict__ W16)
{
    int e = (blockIdx.x * 256 + threadIdx.x) * 4;
    const float* src; __half* dst;
    if (e < NX){ src = x + e; dst = x16 + e; }
    else if (e < NX + NY){ int o = e - NX; src = y + o; dst = y16 + o; }
    else {
        int o = e - NX - NY;
        int w = o / NW, r = o % NW;
        src = (w == 0 ? w0 : w == 1 ? w1 : w == 2 ? w2 : w3) + r;
        dst = W16 + (size_t)w * NW + r;
    }
    float4 v = *reinterpret_cast<const float4*>(src);
    __half2 a = __floats2half2_rn(v.x, v.y);
    __half2 b = __floats2half2_rn(v.z, v.w);
    uint2 o;
    o.x = *reinterpret_cast<uint32_t*>(&a);
    o.y = *reinterpret_cast<uint32_t*>(&b);
    *reinterpret_cast<uint2*>(dst) = o;
}

// ---------------- launch ----------------
extern "C" void kernel_launch(void* const* d_in, const int* in_sizes, int n_in,
                              void* d_out, int out_size)
{
    const float* x  = (const float*)d_in[0];
    const float* y  = (const float*)d_in[1];
    const float* Wq = (const float*)d_in[2];
    const float* Wk = (const float*)d_in[3];
    const float* Wv = (const float*)d_in[4];
    const float* Wo = (const float*)d_in[5];
    const float* bo = (const float*)d_in[6];
    float* out = (float*)d_out;

    __half *x16,*y16,*W16,*WvT16,*Q16,*K16,*Vt16,*E16;
    float *Esum;
    cudaGetSymbolAddress((void**)&x16,   g_x16);
    cudaGetSymbolAddress((void**)&y16,   g_y16);
    cudaGetSymbolAddress((void**)&W16,   g_W16);
    cudaGetSymbolAddress((void**)&WvT16, g_WvT16);
    cudaGetSymbolAddress((void**)&Q16,   g_Q16);
    cudaGetSymbolAddress((void**)&K16,   g_K16);
    cudaGetSymbolAddress((void**)&Vt16,  g_Vt16);
    cudaGetSymbolAddress((void**)&E16,   g_E16);
    cudaGetSymbolAddress((void**)&Esum,  g_Esum);
    __half* Wv16  = W16 + (size_t)2 * NW;   // slot 2: Wv, later overwritten by Wvo
    __half* Wo16  = W16 + (size_t)3 * NW;
    cudaFuncSetAttribute(qkvproj, cudaFuncAttributeMaxDynamicSharedMemorySize, GSMEM);
    cudaFuncSetAttribute(gemmE,   cudaFuncAttributeMaxDynamicSharedMemorySize, GSMEM);
    cudaFuncSetAttribute(gemmAV,  cudaFuncAttributeMaxDynamicSharedMemorySize, GSMEM);
    cudaFuncSetAttribute(gemmW,   cudaFuncAttributeMaxDynamicSharedMemorySize, GSMEM);

    const float sc = 1.0f / sqrtf((float)EMBED);

    cvtAll<<<(NX + NY + 4*NW)/1024, 256>>>(x, y, Wq, Wk, Wv, Wo, x16, y16, W16);
    // WvT = Wv^T ; Wvo = Wo @ Wv  (overwrites W16 slot 2 -> [Wk;Wvo] contiguous)
    trW<<<dim3(16, 16), 256>>>(Wv16, WvT16);
    gemmW<<<dim3(4, 4), 256, GSMEM>>>(Wo16, WvT16, Wv16);
    // Q = x@Wq^T ; K = y@Wk^T ; VO^T = (y@Wvo^T)^T
    qkvproj<<<2560, 256, GSMEM>>>(x16, y16, W16, Q16, K16, Vt16);
    // E = exp(sc * Q K^T) + row partial sums
    gemmE<<<dim3(KLEN/128, QLEN/128, NBATCH), 256, GSMEM>>>(Q16, K16, E16, Esum, sc);
    // out = x + (E @ VOt^T)/rowsum + bo   (final)
    gemmAV<<<dim3(EMBED/128, QLEN/128, NBATCH), 256, GSMEM>>>(E16, Vt16, out, x, bo, Esum);
}

// round 14
// speedup vs baseline: 1.1354x; 1.0624x over previous
#include <cuda_runtime.h>
#include <cuda_fp16.h>
#include <stdint.h>
#include <math.h>

#define EMBED 512
#define NBATCH 8
#define QLEN 2048
#define KLEN 4096
#define MQ (NBATCH*QLEN)
#define MK (NBATCH*KLEN)
#define NBLK (KLEN/128)
#define NW (EMBED*EMBED)

__device__ __half g_x16[MQ*EMBED];
__device__ __half g_y16[MK*EMBED];
__device__ __half g_yT16[(size_t)NBATCH*EMBED*KLEN];
__device__ __half g_W16[4][NW];            // slots: 0 Wq->WqkT, 1 Wk, 2 Wv->Wvo, 3 Wo
__device__ __half g_T1[NW], g_T2[NW];
__device__ __half g_Q16[MQ*EMBED];         // Q', later reused as Z
__device__ __half g_E16[(size_t)MQ*KLEN];
__device__ float  g_Esum[(size_t)MQ*NBLK];

__device__ __forceinline__ uint32_t smem_u32(const void* p){
    uint32_t a;
    asm("{ .reg .u64 t; cvta.to.shared.u64 t, %1; cvt.u32.u64 %0, t; }" : "=r"(a) : "l"(p));
    return a;
}
#define CP16(s,g)   asm volatile("cp.async.cg.shared.global [%0], [%1], 16;" :: "r"(s), "l"(g) : "memory")
#define CP_COMMIT() asm volatile("cp.async.commit_group;" ::: "memory")
#define CP_WAIT1()  asm volatile("cp.async.wait_group 1;" ::: "memory")
#define CP_WAIT0()  asm volatile("cp.async.wait_group 0;" ::: "memory")

__device__ __forceinline__ void ldm4(uint32_t* r, uint32_t a){
    asm volatile("ldmatrix.sync.aligned.m8n8.x4.shared.b16 {%0,%1,%2,%3}, [%4];"
        : "=r"(r[0]), "=r"(r[1]), "=r"(r[2]), "=r"(r[3]) : "r"(a));
}
__device__ __forceinline__ void mma_f16(float* c, const uint32_t* a, const uint32_t* b){
    asm volatile("mma.sync.aligned.m16n8k16.row.col.f32.f16.f16.f32 "
        "{%0,%1,%2,%3}, {%4,%5,%6,%7}, {%8,%9}, {%0,%1,%2,%3};"
        : "+f"(c[0]), "+f"(c[1]), "+f"(c[2]), "+f"(c[3])
        : "r"(a[0]), "r"(a[1]), "r"(a[2]), "r"(a[3]), "r"(b[0]), "r"(b[1]));
}

// ---------------- shared GEMM core (R10/R13 config, frozen) ----------------
// tile 128x128, k64 stage, 3-stage, 1 sync/stage; 8 warps = 4(m) x 2(n); f32 accum.
// EPI 0: fp16 out.   EPI 2: f32 out = acc + resid + bias.
// EPI 3: exp(scale*acc) fp16 + row partial sums.   EPI 4: fp16 out * (1/rowsum).
#define STAGE_B 32768
#define GSMEM   (3*STAGE_B + 1024)

template<int EPI>
__device__ __forceinline__ void gemm_core(
    const __half* __restrict__ A, int lda,
    const __half* __restrict__ B, int ldb, int Kdim,
    int m0, int n0,
    __half* __restrict__ C16, int ldc,
    float* __restrict__ Cf, const float* __restrict__ resid,
    const float* __restrict__ bias, float scale,
    float* __restrict__ esBase, int nblk, char* dynsm)
{
    const uint32_t smbase = smem_u32(dynsm);
    const uint32_t tiles = (smbase + 1023u) & ~1023u;
    const int tid = threadIdx.x, lane = tid & 31, wid = tid >> 5;
    const int wm = wid & 3, wn = wid >> 2;

    float acc[2][8][4];
    #pragma unroll
    for (int i = 0; i < 2; i++)
        #pragma unroll
        for (int j = 0; j < 8; j++)
            #pragma unroll
            for (int k = 0; k < 4; k++) acc[i][j][k] = 0.f;

    const int r_lane = (lane & 7) + ((lane >> 3) & 1) * 8;
    uint32_t aRow[2], aSw[2];
    #pragma unroll
    for (int mt = 0; mt < 2; mt++){
        int m_loc = wm * 32 + mt * 16 + r_lane;
        aRow[mt] = (uint32_t)(m_loc * 128);
        aSw[mt]  = (uint32_t)(m_loc & 7);
    }
    const uint32_t aCk = (lane >> 4) & 1;
    uint32_t bRow[4], bSw[4];
    {
        int n_base = wn * 64 + ((lane >> 4) & 1) * 8 + (lane & 7);
        #pragma unroll
        for (int g = 0; g < 4; g++){
            int n_loc = n_base + g * 16;
            bRow[g] = (uint32_t)(n_loc * 128);
            bSw[g]  = (uint32_t)(n_loc & 7);
        }
    }
    const uint32_t bCk = (lane >> 3) & 1;

    const int C = Kdim >> 6;

    auto load_stage = [&](int c){
        const uint32_t sb = tiles + (c % 3) * STAGE_B;
        const int k0 = c << 6;
        #pragma unroll
        for (int i = 0; i < 4; i++){
            int idx = tid + i * 256;
            int row = idx >> 3, ch = idx & 7;
            uint32_t so = (uint32_t)(row * 128 + ((ch ^ (row & 7)) << 4));
            CP16(sb + so, A + (size_t)(m0 + row) * lda + k0 + ch * 8);
        }
        #pragma unroll
        for (int i = 0; i < 4; i++){
            int idx = tid + i * 256;
            int row = idx >> 3, ch = idx & 7;
            uint32_t so = (uint32_t)(row * 128 + ((ch ^ (row & 7)) << 4));
            CP16(sb + 16384 + so, B + (size_t)(n0 + row) * ldb + k0 + ch * 8);
        }
    };

    load_stage(0); CP_COMMIT();
    load_stage(1); CP_COMMIT();

    for (int c = 0; c < C; c++){
        if (c < C - 1) CP_WAIT1(); else CP_WAIT0();
        __syncthreads();
        if (c + 2 < C){ load_stage(c + 2); CP_COMMIT(); }

        const uint32_t sb = tiles + (c % 3) * STAGE_B;
        #pragma unroll
        for (int ks = 0; ks < 4; ks++){
            uint32_t ah[2][4];
            #pragma unroll
            for (int mt = 0; mt < 2; mt++){
                uint32_t off = aRow[mt] + ((((uint32_t)(2 * ks) + aCk) ^ aSw[mt]) << 4);
                ldm4(ah[mt], sb + off);
            }
            uint32_t bb[8][2];
            #pragma unroll
            for (int g = 0; g < 4; g++){
                uint32_t off = bRow[g] + ((((uint32_t)(2 * ks) + bCk) ^ bSw[g]) << 4);
                uint32_t q[4];
                ldm4(q, sb + 16384 + off);
                bb[2*g][0]=q[0]; bb[2*g][1]=q[1]; bb[2*g+1][0]=q[2]; bb[2*g+1][1]=q[3];
            }
            #pragma unroll
            for (int mt = 0; mt < 2; mt++)
                #pragma unroll
                for (int nf = 0; nf < 8; nf++)
                    mma_f16(acc[mt][nf], ah[mt], bb[nf]);
        }
    }

    const int er = lane >> 2, ec = (lane & 3) * 2;
    if (EPI == 3){
        float* rs = reinterpret_cast<float*>(dynsm + (tiles - smbase));
        float rowp[2][2] = {};
        #pragma unroll
        for (int mt = 0; mt < 2; mt++)
            #pragma unroll
            for (int nf = 0; nf < 8; nf++){
                const int n = n0 + wn * 64 + nf * 8 + ec;
                #pragma unroll
                for (int rr = 0; rr < 2; rr++){
                    const int m = m0 + wm * 32 + mt * 16 + er + rr * 8;
                    float e0 = __expf(acc[mt][nf][rr*2]   * scale);
                    float e1 = __expf(acc[mt][nf][rr*2+1] * scale);
                    __half2 hp = __floats2half2_rn(e0, e1);
                    *reinterpret_cast<uint32_t*>(C16 + (size_t)m * ldc + n) = *reinterpret_cast<uint32_t*>(&hp);
                    rowp[mt][rr] += e0 + e1;
                }
            }
        __syncthreads();
        #pragma unroll
        for (int mt = 0; mt < 2; mt++)
            #pragma unroll
            for (int rr = 0; rr < 2; rr++){
                float v = rowp[mt][rr];
                v += __shfl_xor_sync(0xffffffffu, v, 1);
                v += __shfl_xor_sync(0xffffffffu, v, 2);
                if ((lane & 3) == 0){
                    int row = wm * 32 + mt * 16 + rr * 8 + er;
                    rs[wn * 128 + row] = v;
                }
            }
        __syncthreads();
        if (tid < 128)
            esBase[(size_t)(m0 + tid) * NBLK + nblk] = rs[tid] + rs[128 + tid];
        return;
    }
    if (EPI == 4){
        float invr[2][2];
        #pragma unroll
        for (int mt = 0; mt < 2; mt++)
            #pragma unroll
            for (int rr = 0; rr < 2; rr++){
                const int m = m0 + wm * 32 + mt * 16 + er + rr * 8;
                const float4* p = reinterpret_cast<const float4*>(esBase + (size_t)m * NBLK);
                float s = 0.f;
                #pragma unroll
                for (int i = 0; i < NBLK/4; i++){
                    float4 v = p[i];
                    s += (v.x + v.y) + (v.z + v.w);
                }
                invr[mt][rr] = 1.f / s;
            }
        #pragma unroll
        for (int mt = 0; mt < 2; mt++)
            #pragma unroll
            for (int nf = 0; nf < 8; nf++){
                const int n = n0 + wn * 64 + nf * 8 + ec;
                #pragma unroll
                for (int rr = 0; rr < 2; rr++){
                    const int m = m0 + wm * 32 + mt * 16 + er + rr * 8;
                    __half2 hp = __floats2half2_rn(acc[mt][nf][rr*2]   * invr[mt][rr],
                                                   acc[mt][nf][rr*2+1] * invr[mt][rr]);
                    *reinterpret_cast<uint32_t*>(C16 + (size_t)m * ldc + n) = *reinterpret_cast<uint32_t*>(&hp);
                }
            }
        return;
    }
    if (EPI == 2){
        #pragma unroll
        for (int mt = 0; mt < 2; mt++)
            #pragma unroll
            for (int nf = 0; nf < 8; nf++){
                const int n = n0 + wn * 64 + nf * 8 + ec;
                #pragma unroll
                for (int rr = 0; rr < 2; rr++){
                    const int m = m0 + wm * 32 + mt * 16 + er + rr * 8;
                    size_t off = (size_t)m * ldc + n;
                    float2 rv = *reinterpret_cast<const float2*>(resid + off);
                    float2 bv = *reinterpret_cast<const float2*>(bias + n);
                    float2 o;
                    o.x = acc[mt][nf][rr*2]   + rv.x + bv.x;
                    o.y = acc[mt][nf][rr*2+1] + rv.y + bv.y;
                    *reinterpret_cast<float2*>(Cf + off) = o;
                }
            }
        return;
    }
    // EPI 0
    #pragma unroll
    for (int mt = 0; mt < 2; mt++)
        #pragma unroll
        for (int nf = 0; nf < 8; nf++){
            const int n = n0 + wn * 64 + nf * 8 + ec;
            #pragma unroll
            for (int rr = 0; rr < 2; rr++){
                const int m = m0 + wm * 32 + mt * 16 + er + rr * 8;
                __half2 hp = __floats2half2_rn(acc[mt][nf][rr*2], acc[mt][nf][rr*2+1]);
                *reinterpret_cast<uint32_t*>(C16 + (size_t)m * ldc + n) = *reinterpret_cast<uint32_t*>(&hp);
            }
        }
}

// ---------------- kernels ----------------
// Q' = x @ WqkT^T   (effective Q' = x @ Wqk)
__global__ void __launch_bounds__(256, 2)
qproj(const __half* __restrict__ x16, const __half* __restrict__ WqkT,
      __half* __restrict__ Q16)
{
    extern __shared__ char dynsm[];
    gemm_core<0>(x16, EMBED, WqkT, EMBED, EMBED,
                 (blockIdx.x >> 2) * 128, (blockIdx.x & 3) * 128,
                 Q16, EMBED, nullptr, nullptr, nullptr, 1.0f, nullptr, 0, dynsm);
}

// E = exp(sc * Q' y^T) + row partial sums
__global__ void __launch_bounds__(256, 2)
gemmE(const __half* __restrict__ Q16, const __half* __restrict__ y16,
      __half* __restrict__ E16, float* __restrict__ Esum, float scale)
{
    extern __shared__ char dynsm[];
    const int b = blockIdx.z;
    gemm_core<3>(Q16 + (size_t)b * QLEN * EMBED, EMBED,
                 y16 + (size_t)b * KLEN * EMBED, EMBED, EMBED,
                 blockIdx.y * 128, blockIdx.x * 128,
                 E16 + (size_t)b * QLEN * KLEN, KLEN,
                 nullptr, nullptr, nullptr, scale,
                 Esum + (size_t)b * QLEN * NBLK, blockIdx.x, dynsm);
}

// Z = (E @ yT^T) * (1/rowsum)    [= A @ y, normalized]
__global__ void __launch_bounds__(256, 2)
gemmZ(const __half* __restrict__ E16, const __half* __restrict__ yT16,
      __half* __restrict__ Z16, const float* __restrict__ Esum)
{
    extern __shared__ char dynsm[];
    const int b = blockIdx.z;
    gemm_core<4>(E16 + (size_t)b * QLEN * KLEN, KLEN,
                 yT16 + (size_t)b * EMBED * KLEN, KLEN, KLEN,
                 blockIdx.y * 128, blockIdx.x * 128,
                 Z16 + (size_t)b * QLEN * EMBED, EMBED,
                 nullptr, nullptr, nullptr, 1.0f,
                 const_cast<float*>(Esum) + (size_t)b * QLEN * NBLK, 0, dynsm);
}

// out = x + Z @ Wvo^T + bo
__global__ void __launch_bounds__(256, 2)
gemmOut(const __half* __restrict__ Z16, const __half* __restrict__ Wvo,
        float* __restrict__ out, const float* __restrict__ x, const float* __restrict__ bo)
{
    extern __shared__ char dynsm[];
    gemm_core<2>(Z16, EMBED, Wvo, EMBED, EMBED,
                 (blockIdx.x >> 2) * 128, (blockIdx.x & 3) * 128,
                 nullptr, EMBED, out, x, bo, 1.0f, nullptr, 0, dynsm);
}

// small 512^2 GEMM for weight products (fp16 out)
__global__ void __launch_bounds__(256, 2)
gemmW(const __half* __restrict__ A, const __half* __restrict__ B, __half* __restrict__ D)
{
    extern __shared__ char dynsm[];
    gemm_core<0>(A, EMBED, B, EMBED, EMBED,
                 blockIdx.y * 128, blockIdx.x * 128,
                 D, EMBED, nullptr, nullptr, nullptr, 1.0f, nullptr, 0, dynsm);
}

// transpose 512x512 fp16
__global__ void __launch_bounds__(256, 1)
trW(const __half* __restrict__ src, __half* __restrict__ dst)
{
    __shared__ __half s[32][33];
    const int x0 = blockIdx.x * 32, y0 = blockIdx.y * 32;
    const int tx = threadIdx.x & 31, ty = threadIdx.x >> 5;
    #pragma unroll
    for (int i = ty; i < 32; i += 8)
        s[i][tx] = src[(size_t)(y0 + i) * EMBED + x0 + tx];
    __syncthreads();
    #pragma unroll
    for (int i = ty; i < 32; i += 8)
        dst[(size_t)(x0 + i) * EMBED + y0 + tx] = s[tx][i];
}

// convert x + 4 weights to fp16
#define NXE (MQ*EMBED)
__global__ void __launch_bounds__(256, 1)
cvtXW(const float* __restrict__ x,
      const float* __restrict__ w0, const float* __restrict__ w1,
      const float* __restrict__ w2, const float* __restrict__ w3,
      __half* __restrict__ x16, __half* __restrict__ W16)
{
    int e = (blockIdx.x * 256 + threadIdx.x) * 4;
    const float* src; __half* dst;
    if (e < NXE){ src = x + e; dst = x16 + e; }
    else {
        int o = e - NXE;
        int w = o / NW, r = o % NW;
        src = (w == 0 ? w0 : w == 1 ? w1 : w == 2 ? w2 : w3) + r;
        dst = W16 + (size_t)w * NW + r;
    }
    float4 v = *reinterpret_cast<const float4*>(src);
    __half2 a = __floats2half2_rn(v.x, v.y);
    __half2 b = __floats2half2_rn(v.z, v.w);
    uint2 o;
    o.x = *reinterpret_cast<uint32_t*>(&a);
    o.y = *reinterpret_cast<uint32_t*>(&b);
    *reinterpret_cast<uint2*>(dst) = o;
}

// convert y -> y16 AND yT16 (transposed) in one pass
__global__ void __launch_bounds__(256, 1)
cvtY(const float* __restrict__ y, __half* __restrict__ y16, __half* __restrict__ yT16)
{
    __shared__ __half s[32][33];
    const int b = blockIdx.z, kk0 = blockIdx.x * 32, d0 = blockIdx.y * 32;
    const int tx = threadIdx.x & 31, ty = threadIdx.x >> 5;
    const float* src = y + (size_t)b * KLEN * EMBED;
    __half* d1 = y16 + (size_t)b * KLEN * EMBED;
    #pragma unroll
    for (int i = ty; i < 32; i += 8){
        __half h = __float2half(src[(size_t)(kk0 + i) * EMBED + d0 + tx]);
        d1[(size_t)(kk0 + i) * EMBED + d0 + tx] = h;
        s[i][tx] = h;
    }
    __syncthreads();
    __half* d2 = yT16 + (size_t)b * EMBED * KLEN;
    #pragma unroll
    for (int i = ty; i < 32; i += 8)
        d2[(size_t)(d0 + i) * KLEN + kk0 + tx] = s[tx][i];
}

// ---------------- launch ----------------
extern "C" void kernel_launch(void* const* d_in, const int* in_sizes, int n_in,
                              void* d_out, int out_size)
{
    const float* x  = (const float*)d_in[0];
    const float* y  = (const float*)d_in[1];
    const float* Wq = (const float*)d_in[2];
    const float* Wk = (const float*)d_in[3];
    const float* Wv = (const float*)d_in[4];
    const float* Wo = (const float*)d_in[5];
    const float* bo = (const float*)d_in[6];
    float* out = (float*)d_out;

    __half *x16,*y16,*yT16,*W16,*T1,*T2,*Q16,*E16;
    float *Esum;
    cudaGetSymbolAddress((void**)&x16,  g_x16);
    cudaGetSymbolAddress((void**)&y16,  g_y16);
    cudaGetSymbolAddress((void**)&yT16, g_yT16);
    cudaGetSymbolAddress((void**)&W16,  g_W16);
    cudaGetSymbolAddress((void**)&T1,   g_T1);
    cudaGetSymbolAddress((void**)&T2,   g_T2);
    cudaGetSymbolAddress((void**)&Q16,  g_Q16);
    cudaGetSymbolAddress((void**)&E16,  g_E16);
    cudaGetSymbolAddress((void**)&Esum, g_Esum);
    __half* Wq16 = W16;                       // -> WqkT after gemmW
    __half* Wk16 = W16 + (size_t)NW;
    __half* Wv16 = W16 + (size_t)2 * NW;      // -> Wvo after gemmW
    __half* Wo16 = W16 + (size_t)3 * NW;
    cudaFuncSetAttribute(qproj,  cudaFuncAttributeMaxDynamicSharedMemorySize, GSMEM);
    cudaFuncSetAttribute(gemmE,  cudaFuncAttributeMaxDynamicSharedMemorySize, GSMEM);
    cudaFuncSetAttribute(gemmZ,  cudaFuncAttributeMaxDynamicSharedMemorySize, GSMEM);
    cudaFuncSetAttribute(gemmOut,cudaFuncAttributeMaxDynamicSharedMemorySize, GSMEM);
    cudaFuncSetAttribute(gemmW,  cudaFuncAttributeMaxDynamicSharedMemorySize, GSMEM);

    const float sc = 1.0f / sqrtf((float)EMBED);

    // converts (x, W) and (y -> y16 + yT16)
    cvtXW<<<(NXE + 4*NW)/1024, 256>>>(x, Wq, Wk, Wv, Wo, x16, W16);
    cvtY<<<dim3(KLEN/32, EMBED/32, NBATCH), 256>>>(y, y16, yT16);
    // weight products: WqkT = Wk^T @ Wq (so Q' = x @ Wqk);  Wvo = Wo @ Wv
    trW<<<dim3(16,16), 256>>>(Wq16, T1);           // T1 = WqT
    trW<<<dim3(16,16), 256>>>(Wk16, T2);           // T2 = WkT
    gemmW<<<dim3(4,4), 256, GSMEM>>>(T2, T1, Wq16);  // WqkT[d][k] = sum_j WkT[d][j]*WqT[k][j]
    trW<<<dim3(16,16), 256>>>(Wv16, T1);           // T1 = WvT
    gemmW<<<dim3(4,4), 256, GSMEM>>>(Wo16, T1, Wv16); // Wvo = Wo @ Wv
    // Q' = x @ Wqk
    qproj<<<512, 256, GSMEM>>>(x16, Wq16, Q16);
    // E = exp(sc * Q' y^T) + row sums
    gemmE<<<dim3(KLEN/128, QLEN/128, NBATCH), 256, GSMEM>>>(Q16, y16, E16, Esum, sc);
    // Z = (E @ yT^T) * inv  -> reuse Q16 buffer
    gemmZ<<<dim3(EMBED/128, QLEN/128, NBATCH), 256, GSMEM>>>(E16, yT16, Q16, Esum);
    // out = x + Z @ Wvo^T + bo
    gemmOut<<<512, 256, GSMEM>>>(Q16, Wv16, out, x, bo);
}

// round 15
// speedup vs baseline: 1.1657x; 1.0267x over previous
#include <cuda_runtime.h>
#include <cuda_fp16.h>
#include <stdint.h>
#include <math.h>

#define EMBED 512
#define NBATCH 8
#define QLEN 2048
#define KLEN 4096
#define MQ (NBATCH*QLEN)
#define MK (NBATCH*KLEN)
#define NBLK (KLEN/128)
#define NW (EMBED*EMBED)

__device__ __half g_x16[MQ*EMBED];
__device__ __half g_y16[MK*EMBED];
__device__ __half g_yT16[(size_t)NBATCH*EMBED*KLEN];
__device__ __half g_W16[4][NW];            // 0 Wq->WqkT, 1 Wk, 2 Wv->Wvo, 3 Wo
__device__ __half g_T1[NW], g_T2[NW], g_T3[NW];
__device__ __half g_Q16[MQ*EMBED];         // Q', later reused as Z
__device__ __half g_E16[(size_t)MQ*KLEN];
__device__ float  g_Esum[(size_t)MQ*NBLK];

__device__ __forceinline__ uint32_t smem_u32(const void* p){
    uint32_t a;
    asm("{ .reg .u64 t; cvta.to.shared.u64 t, %1; cvt.u32.u64 %0, t; }" : "=r"(a) : "l"(p));
    return a;
}
#define CP16(s,g)   asm volatile("cp.async.cg.shared.global [%0], [%1], 16;" :: "r"(s), "l"(g) : "memory")
#define CP_COMMIT() asm volatile("cp.async.commit_group;" ::: "memory")
#define CP_WAIT1()  asm volatile("cp.async.wait_group 1;" ::: "memory")
#define CP_WAIT0()  asm volatile("cp.async.wait_group 0;" ::: "memory")

__device__ __forceinline__ void ldm4(uint32_t* r, uint32_t a){
    asm volatile("ldmatrix.sync.aligned.m8n8.x4.shared.b16 {%0,%1,%2,%3}, [%4];"
        : "=r"(r[0]), "=r"(r[1]), "=r"(r[2]), "=r"(r[3]) : "r"(a));
}
__device__ __forceinline__ void mma_f16(float* c, const uint32_t* a, const uint32_t* b){
    asm volatile("mma.sync.aligned.m16n8k16.row.col.f32.f16.f16.f32 "
        "{%0,%1,%2,%3}, {%4,%5,%6,%7}, {%8,%9}, {%0,%1,%2,%3};"
        : "+f"(c[0]), "+f"(c[1]), "+f"(c[2]), "+f"(c[3])
        : "r"(a[0]), "r"(a[1]), "r"(a[2]), "r"(a[3]), "r"(b[0]), "r"(b[1]));
}

// ---------------- shared GEMM core (frozen R10/R13 config) ----------------
// tile 128x128, k64 stage, 3-stage, 1 sync/stage; 8 warps = 4(m) x 2(n); f32 accum.
// EPI 0: fp16 out.  EPI 2: f32 = acc + resid + bias.
// EPI 3: exp(scale*acc) fp16 + row partial sums.  EPI 4: fp16 * (1/rowsum).
#define STAGE_B 32768
#define GSMEM   (3*STAGE_B + 1024)

template<int EPI>
__device__ __forceinline__ void gemm_core(
    const __half* __restrict__ A, int lda,
    const __half* __restrict__ B, int ldb, int Kdim,
    int m0, int n0,
    __half* __restrict__ C16, int ldc,
    float* __restrict__ Cf, const float* __restrict__ resid,
    const float* __restrict__ bias, float scale,
    float* __restrict__ esBase, int nblk, char* dynsm)
{
    const uint32_t smbase = smem_u32(dynsm);
    const uint32_t tiles = (smbase + 1023u) & ~1023u;
    const int tid = threadIdx.x, lane = tid & 31, wid = tid >> 5;
    const int wm = wid & 3, wn = wid >> 2;

    float acc[2][8][4];
    #pragma unroll
    for (int i = 0; i < 2; i++)
        #pragma unroll
        for (int j = 0; j < 8; j++)
            #pragma unroll
            for (int k = 0; k < 4; k++) acc[i][j][k] = 0.f;

    const int r_lane = (lane & 7) + ((lane >> 3) & 1) * 8;
    uint32_t aRow[2], aSw[2];
    #pragma unroll
    for (int mt = 0; mt < 2; mt++){
        int m_loc = wm * 32 + mt * 16 + r_lane;
        aRow[mt] = (uint32_t)(m_loc * 128);
        aSw[mt]  = (uint32_t)(m_loc & 7);
    }
    const uint32_t aCk = (lane >> 4) & 1;
    uint32_t bRow[4], bSw[4];
    {
        int n_base = wn * 64 + ((lane >> 4) & 1) * 8 + (lane & 7);
        #pragma unroll
        for (int g = 0; g < 4; g++){
            int n_loc = n_base + g * 16;
            bRow[g] = (uint32_t)(n_loc * 128);
            bSw[g]  = (uint32_t)(n_loc & 7);
        }
    }
    const uint32_t bCk = (lane >> 3) & 1;

    const int C = Kdim >> 6;

    auto load_stage = [&](int c){
        const uint32_t sb = tiles + (c % 3) * STAGE_B;
        const int k0 = c << 6;
        #pragma unroll
        for (int i = 0; i < 4; i++){
            int idx = tid + i * 256;
            int row = idx >> 3, ch = idx & 7;
            uint32_t so = (uint32_t)(row * 128 + ((ch ^ (row & 7)) << 4));
            CP16(sb + so, A + (size_t)(m0 + row) * lda + k0 + ch * 8);
        }
        #pragma unroll
        for (int i = 0; i < 4; i++){
            int idx = tid + i * 256;
            int row = idx >> 3, ch = idx & 7;
            uint32_t so = (uint32_t)(row * 128 + ((ch ^ (row & 7)) << 4));
            CP16(sb + 16384 + so, B + (size_t)(n0 + row) * ldb + k0 + ch * 8);
        }
    };

    load_stage(0); CP_COMMIT();
    load_stage(1); CP_COMMIT();

    for (int c = 0; c < C; c++){
        if (c < C - 1) CP_WAIT1(); else CP_WAIT0();
        __syncthreads();
        if (c + 2 < C){ load_stage(c + 2); CP_COMMIT(); }

        const uint32_t sb = tiles + (c % 3) * STAGE_B;
        #pragma unroll
        for (int ks = 0; ks < 4; ks++){
            uint32_t ah[2][4];
            #pragma unroll
            for (int mt = 0; mt < 2; mt++){
                uint32_t off = aRow[mt] + ((((uint32_t)(2 * ks) + aCk) ^ aSw[mt]) << 4);
                ldm4(ah[mt], sb + off);
            }
            uint32_t bb[8][2];
            #pragma unroll
            for (int g = 0; g < 4; g++){
                uint32_t off = bRow[g] + ((((uint32_t)(2 * ks) + bCk) ^ bSw[g]) << 4);
                uint32_t q[4];
                ldm4(q, sb + 16384 + off);
                bb[2*g][0]=q[0]; bb[2*g][1]=q[1]; bb[2*g+1][0]=q[2]; bb[2*g+1][1]=q[3];
            }
            #pragma unroll
            for (int mt = 0; mt < 2; mt++)
                #pragma unroll
                for (int nf = 0; nf < 8; nf++)
                    mma_f16(acc[mt][nf], ah[mt], bb[nf]);
        }
    }

    const int er = lane >> 2, ec = (lane & 3) * 2;
    if (EPI == 3){
        float* rs = reinterpret_cast<float*>(dynsm + (tiles - smbase));
        float rowp[2][2] = {};
        #pragma unroll
        for (int mt = 0; mt < 2; mt++)
            #pragma unroll
            for (int nf = 0; nf < 8; nf++){
                const int n = n0 + wn * 64 + nf * 8 + ec;
                #pragma unroll
                for (int rr = 0; rr < 2; rr++){
                    const int m = m0 + wm * 32 + mt * 16 + er + rr * 8;
                    float e0 = __expf(acc[mt][nf][rr*2]   * scale);
                    float e1 = __expf(acc[mt][nf][rr*2+1] * scale);
                    __half2 hp = __floats2half2_rn(e0, e1);
                    *reinterpret_cast<uint32_t*>(C16 + (size_t)m * ldc + n) = *reinterpret_cast<uint32_t*>(&hp);
                    rowp[mt][rr] += e0 + e1;
                }
            }
        __syncthreads();
        #pragma unroll
        for (int mt = 0; mt < 2; mt++)
            #pragma unroll
            for (int rr = 0; rr < 2; rr++){
                float v = rowp[mt][rr];
                v += __shfl_xor_sync(0xffffffffu, v, 1);
                v += __shfl_xor_sync(0xffffffffu, v, 2);
                if ((lane & 3) == 0){
                    int row = wm * 32 + mt * 16 + rr * 8 + er;
                    rs[wn * 128 + row] = v;
                }
            }
        __syncthreads();
        if (tid < 128)
            esBase[(size_t)(m0 + tid) * NBLK + nblk] = rs[tid] + rs[128 + tid];
        return;
    }
    if (EPI == 4){
        float invr[2][2];
        #pragma unroll
        for (int mt = 0; mt < 2; mt++)
            #pragma unroll
            for (int rr = 0; rr < 2; rr++){
                const int m = m0 + wm * 32 + mt * 16 + er + rr * 8;
                const float4* p = reinterpret_cast<const float4*>(esBase + (size_t)m * NBLK);
                float s = 0.f;
                #pragma unroll
                for (int i = 0; i < NBLK/4; i++){
                    float4 v = p[i];
                    s += (v.x + v.y) + (v.z + v.w);
                }
                invr[mt][rr] = 1.f / s;
            }
        #pragma unroll
        for (int mt = 0; mt < 2; mt++)
            #pragma unroll
            for (int nf = 0; nf < 8; nf++){
                const int n = n0 + wn * 64 + nf * 8 + ec;
                #pragma unroll
                for (int rr = 0; rr < 2; rr++){
                    const int m = m0 + wm * 32 + mt * 16 + er + rr * 8;
                    __half2 hp = __floats2half2_rn(acc[mt][nf][rr*2]   * invr[mt][rr],
                                                   acc[mt][nf][rr*2+1] * invr[mt][rr]);
                    *reinterpret_cast<uint32_t*>(C16 + (size_t)m * ldc + n) = *reinterpret_cast<uint32_t*>(&hp);
                }
            }
        return;
    }
    if (EPI == 2){
        #pragma unroll
        for (int mt = 0; mt < 2; mt++)
            #pragma unroll
            for (int nf = 0; nf < 8; nf++){
                const int n = n0 + wn * 64 + nf * 8 + ec;
                #pragma unroll
                for (int rr = 0; rr < 2; rr++){
                    const int m = m0 + wm * 32 + mt * 16 + er + rr * 8;
                    size_t off = (size_t)m * ldc + n;
                    float2 rv = *reinterpret_cast<const float2*>(resid + off);
                    float2 bv = *reinterpret_cast<const float2*>(bias + n);
                    float2 o;
                    o.x = acc[mt][nf][rr*2]   + rv.x + bv.x;
                    o.y = acc[mt][nf][rr*2+1] + rv.y + bv.y;
                    *reinterpret_cast<float2*>(Cf + off) = o;
                }
            }
        return;
    }
    // EPI 0
    #pragma unroll
    for (int mt = 0; mt < 2; mt++)
        #pragma unroll
        for (int nf = 0; nf < 8; nf++){
            const int n = n0 + wn * 64 + nf * 8 + ec;
            #pragma unroll
            for (int rr = 0; rr < 2; rr++){
                const int m = m0 + wm * 32 + mt * 16 + er + rr * 8;
                __half2 hp = __floats2half2_rn(acc[mt][nf][rr*2], acc[mt][nf][rr*2+1]);
                *reinterpret_cast<uint32_t*>(C16 + (size_t)m * ldc + n) = *reinterpret_cast<uint32_t*>(&hp);
            }
        }
}

// ---------------- kernels ----------------
__global__ void __launch_bounds__(256, 2)
qproj(const __half* __restrict__ x16, const __half* __restrict__ WqkT,
      __half* __restrict__ Q16)
{
    extern __shared__ char dynsm[];
    gemm_core<0>(x16, EMBED, WqkT, EMBED, EMBED,
                 (blockIdx.x >> 2) * 128, (blockIdx.x & 3) * 128,
                 Q16, EMBED, nullptr, nullptr, nullptr, 1.0f, nullptr, 0, dynsm);
}

__global__ void __launch_bounds__(256, 2)
gemmE(const __half* __restrict__ Q16, const __half* __restrict__ y16,
      __half* __restrict__ E16, float* __restrict__ Esum, float scale)
{
    extern __shared__ char dynsm[];
    const int b = blockIdx.z;
    gemm_core<3>(Q16 + (size_t)b * QLEN * EMBED, EMBED,
                 y16 + (size_t)b * KLEN * EMBED, EMBED, EMBED,
                 blockIdx.y * 128, blockIdx.x * 128,
                 E16 + (size_t)b * QLEN * KLEN, KLEN,
                 nullptr, nullptr, nullptr, scale,
                 Esum + (size_t)b * QLEN * NBLK, blockIdx.x, dynsm);
}

__global__ void __launch_bounds__(256, 2)
gemmZ(const __half* __restrict__ E16, const __half* __restrict__ yT16,
      __half* __restrict__ Z16, const float* __restrict__ Esum)
{
    extern __shared__ char dynsm[];
    const int b = blockIdx.z;
    gemm_core<4>(E16 + (size_t)b * QLEN * KLEN, KLEN,
                 yT16 + (size_t)b * EMBED * KLEN, KLEN, KLEN,
                 blockIdx.y * 128, blockIdx.x * 128,
                 Z16 + (size_t)b * QLEN * EMBED, EMBED,
                 nullptr, nullptr, nullptr, 1.0f,
                 const_cast<float*>(Esum) + (size_t)b * QLEN * NBLK, 0, dynsm);
}

__global__ void __launch_bounds__(256, 2)
gemmOut(const __half* __restrict__ Z16, const __half* __restrict__ Wvo,
        float* __restrict__ out, const float* __restrict__ x, const float* __restrict__ bo)
{
    extern __shared__ char dynsm[];
    gemm_core<2>(Z16, EMBED, Wvo, EMBED, EMBED,
                 (blockIdx.x >> 2) * 128, (blockIdx.x & 3) * 128,
                 nullptr, EMBED, out, x, bo, 1.0f, nullptr, 0, dynsm);
}

// merged weight products: z=0 -> WqkT = T2 @ T1^T ; z=1 -> Wvo = Wo @ T3^T
__global__ void __launch_bounds__(256, 2)
gemmW2(const __half* __restrict__ T1, const __half* __restrict__ T2,
       const __half* __restrict__ T3, const __half* __restrict__ Wo,
       __half* __restrict__ WqkT, __half* __restrict__ Wvo)
{
    extern __shared__ char dynsm[];
    const __half* A; const __half* B; __half* D;
    if (blockIdx.z == 0){ A = T2; B = T1; D = WqkT; }
    else                { A = Wo; B = T3; D = Wvo;  }
    gemm_core<0>(A, EMBED, B, EMBED, EMBED,
                 blockIdx.y * 128, blockIdx.x * 128,
                 D, EMBED, nullptr, nullptr, nullptr, 1.0f, nullptr, 0, dynsm);
}

// merged transposes: z selects Wq->T1, Wk->T2, Wv->T3
__global__ void __launch_bounds__(256, 1)
trW3(const __half* __restrict__ Wq, const __half* __restrict__ Wk,
     const __half* __restrict__ Wv,
     __half* __restrict__ T1, __half* __restrict__ T2, __half* __restrict__ T3)
{
    __shared__ __half s[32][33];
    const __half* src = (blockIdx.z == 0) ? Wq : (blockIdx.z == 1) ? Wk : Wv;
    __half*       dst = (blockIdx.z == 0) ? T1 : (blockIdx.z == 1) ? T2 : T3;
    const int x0 = blockIdx.x * 32, y0 = blockIdx.y * 32;
    const int tx = threadIdx.x & 31, ty = threadIdx.x >> 5;
    #pragma unroll
    for (int i = ty; i < 32; i += 8)
        s[i][tx] = src[(size_t)(y0 + i) * EMBED + x0 + tx];
    __syncthreads();
    #pragma unroll
    for (int i = ty; i < 32; i += 8)
        dst[(size_t)(x0 + i) * EMBED + y0 + tx] = s[tx][i];
}

// convert x + 4 weights to fp16
#define NXE (MQ*EMBED)
__global__ void __launch_bounds__(256, 1)
cvtXW(const float* __restrict__ x,
      const float* __restrict__ w0, const float* __restrict__ w1,
      const float* __restrict__ w2, const float* __restrict__ w3,
      __half* __restrict__ x16, __half* __restrict__ W16)
{
    int e = (blockIdx.x * 256 + threadIdx.x) * 4;
    const float* src; __half* dst;
    if (e < NXE){ src = x + e; dst = x16 + e; }
    else {
        int o = e - NXE;
        int w = o / NW, r = o % NW;
        src = (w == 0 ? w0 : w == 1 ? w1 : w == 2 ? w2 : w3) + r;
        dst = W16 + (size_t)w * NW + r;
    }
    float4 v = *reinterpret_cast<const float4*>(src);
    __half2 a = __floats2half2_rn(v.x, v.y);
    __half2 b = __floats2half2_rn(v.z, v.w);
    uint2 o;
    o.x = *reinterpret_cast<uint32_t*>(&a);
    o.y = *reinterpret_cast<uint32_t*>(&b);
    *reinterpret_cast<uint2*>(dst) = o;
}

// convert y -> y16 AND yT16 (transposed) in one pass
__global__ void __launch_bounds__(256, 1)
cvtY(const float* __restrict__ y, __half* __restrict__ y16, __half* __restrict__ yT16)
{
    __shared__ __half s[32][33];
    const int b = blockIdx.z, kk0 = blockIdx.x * 32, d0 = blockIdx.y * 32;
    const int tx = threadIdx.x & 31, ty = threadIdx.x >> 5;
    const float* src = y + (size_t)b * KLEN * EMBED;
    __half* d1 = y16 + (size_t)b * KLEN * EMBED;
    #pragma unroll
    for (int i = ty; i < 32; i += 8){
        __half h = __float2half(src[(size_t)(kk0 + i) * EMBED + d0 + tx]);
        d1[(size_t)(kk0 + i) * EMBED + d0 + tx] = h;
        s[i][tx] = h;
    }
    __syncthreads();
    __half* d2 = yT16 + (size_t)b * EMBED * KLEN;
    #pragma unroll
    for (int i = ty; i < 32; i += 8)
        d2[(size_t)(d0 + i) * KLEN + kk0 + tx] = s[tx][i];
}

// ---------------- launch ----------------
extern "C" void kernel_launch(void* const* d_in, const int* in_sizes, int n_in,
                              void* d_out, int out_size)
{
    const float* x  = (const float*)d_in[0];
    const float* y  = (const float*)d_in[1];
    const float* Wq = (const float*)d_in[2];
    const float* Wk = (const float*)d_in[3];
    const float* Wv = (const float*)d_in[4];
    const float* Wo = (const float*)d_in[5];
    const float* bo = (const float*)d_in[6];
    float* out = (float*)d_out;

    __half *x16,*y16,*yT16,*W16,*T1,*T2,*T3,*Q16,*E16;
    float *Esum;
    cudaGetSymbolAddress((void**)&x16,  g_x16);
    cudaGetSymbolAddress((void**)&y16,  g_y16);
    cudaGetSymbolAddress((void**)&yT16, g_yT16);
    cudaGetSymbolAddress((void**)&W16,  g_W16);
    cudaGetSymbolAddress((void**)&T1,   g_T1);
    cudaGetSymbolAddress((void**)&T2,   g_T2);
    cudaGetSymbolAddress((void**)&T3,   g_T3);
    cudaGetSymbolAddress((void**)&Q16,  g_Q16);
    cudaGetSymbolAddress((void**)&E16,  g_E16);
    cudaGetSymbolAddress((void**)&Esum, g_Esum);
    __half* Wq16 = W16;                       // -> WqkT
    __half* Wk16 = W16 + (size_t)NW;
    __half* Wv16 = W16 + (size_t)2 * NW;      // -> Wvo
    __half* Wo16 = W16 + (size_t)3 * NW;
    cudaFuncSetAttribute(qproj,  cudaFuncAttributeMaxDynamicSharedMemorySize, GSMEM);
    cudaFuncSetAttribute(gemmE,  cudaFuncAttributeMaxDynamicSharedMemorySize, GSMEM);
    cudaFuncSetAttribute(gemmZ,  cudaFuncAttributeMaxDynamicSharedMemorySize, GSMEM);
    cudaFuncSetAttribute(gemmOut,cudaFuncAttributeMaxDynamicSharedMemorySize, GSMEM);
    cudaFuncSetAttribute(gemmW2, cudaFuncAttributeMaxDynamicSharedMemorySize, GSMEM);

    const float sc = 1.0f / sqrtf((float)EMBED);

    cvtXW<<<(NXE + 4*NW)/1024, 256>>>(x, Wq, Wk, Wv, Wo, x16, W16);
    cvtY<<<dim3(KLEN/32, EMBED/32, NBATCH), 256>>>(y, y16, yT16);
    // merged transposes + merged weight products
    trW3<<<dim3(16,16,3), 256>>>(Wq16, Wk16, Wv16, T1, T2, T3);
    gemmW2<<<dim3(4,4,2), 256, GSMEM>>>(T1, T2, T3, Wo16, Wq16, Wv16);
    // Q' = x @ Wqk
    qproj<<<512, 256, GSMEM>>>(x16, Wq16, Q16);
    // E = exp(sc * Q' y^T) + row sums
    gemmE<<<dim3(KLEN/128, QLEN/128, NBATCH), 256, GSMEM>>>(Q16, y16, E16, Esum, sc);
    // Z = (E @ yT^T) * inv  -> reuse Q16
    gemmZ<<<dim3(EMBED/128, QLEN/128, NBATCH), 256, GSMEM>>>(E16, yT16, Q16, Esum);
    // out = x + Z @ Wvo^T + bo
    gemmOut<<<512, 256, GSMEM>>>(Q16, Wv16, out, x, bo);
}

// round 16
// speedup vs baseline: 1.2026x; 1.0317x over previous
#include <cuda_runtime.h>
#include <cuda_fp16.h>
#include <stdint.h>
#include <math.h>

#define EMBED 512
#define NBATCH 8
#define QLEN 2048
#define KLEN 4096
#define MQ (NBATCH*QLEN)
#define MK (NBATCH*KLEN)
#define NBLK (KLEN/128)
#define NW (EMBED*EMBED)

__device__ __half g_x16[MQ*EMBED];
__device__ __half g_y16[MK*EMBED];
__device__ __half g_yT16[(size_t)NBATCH*EMBED*KLEN];
__device__ __half g_W16[4][NW];            // 0 Wq->WqkT, 1 Wk, 2 Wv->Wvo, 3 Wo
__device__ __half g_T1[NW], g_T2[NW], g_T3[NW];
__device__ __half g_Q16[MQ*EMBED];         // Q', later reused as Z
__device__ __half g_E16[(size_t)MQ*KLEN];
__device__ float  g_Esum[(size_t)MQ*NBLK];
__device__ int    g_cnt[384];              // [0,128): qcnt, [128,256): ecnt, [256,384): zcnt

__device__ __forceinline__ uint32_t smem_u32(const void* p){
    uint32_t a;
    asm("{ .reg .u64 t; cvta.to.shared.u64 t, %1; cvt.u32.u64 %0, t; }" : "=r"(a) : "l"(p));
    return a;
}
#define CP16(s,g)   asm volatile("cp.async.cg.shared.global [%0], [%1], 16;" :: "r"(s), "l"(g) : "memory")
#define CP_COMMIT() asm volatile("cp.async.commit_group;" ::: "memory")
#define CP_WAIT1()  asm volatile("cp.async.wait_group 1;" ::: "memory")
#define CP_WAIT0()  asm volatile("cp.async.wait_group 0;" ::: "memory")

__device__ __forceinline__ void ldm4(uint32_t* r, uint32_t a){
    asm volatile("ldmatrix.sync.aligned.m8n8.x4.shared.b16 {%0,%1,%2,%3}, [%4];"
        : "=r"(r[0]), "=r"(r[1]), "=r"(r[2]), "=r"(r[3]) : "r"(a));
}
__device__ __forceinline__ void mma_f16(float* c, const uint32_t* a, const uint32_t* b){
    asm volatile("mma.sync.aligned.m16n8k16.row.col.f32.f16.f16.f32 "
        "{%0,%1,%2,%3}, {%4,%5,%6,%7}, {%8,%9}, {%0,%1,%2,%3};"
        : "+f"(c[0]), "+f"(c[1]), "+f"(c[2]), "+f"(c[3])
        : "r"(a[0]), "r"(a[1]), "r"(a[2]), "r"(a[3]), "r"(b[0]), "r"(b[1]));
}

// ---------------- shared GEMM core (frozen R10/R13 config) ----------------
#define STAGE_B 32768
#define GSMEM   (3*STAGE_B + 1024)

template<int EPI>
__device__ __forceinline__ void gemm_core(
    const __half* __restrict__ A, int lda,
    const __half* __restrict__ B, int ldb, int Kdim,
    int m0, int n0,
    __half* __restrict__ C16, int ldc,
    float* __restrict__ Cf, const float* __restrict__ resid,
    const float* __restrict__ bias, float scale,
    float* __restrict__ esBase, int nblk, char* dynsm)
{
    const uint32_t smbase = smem_u32(dynsm);
    const uint32_t tiles = (smbase + 1023u) & ~1023u;
    const int tid = threadIdx.x, lane = tid & 31, wid = tid >> 5;
    const int wm = wid & 3, wn = wid >> 2;

    float acc[2][8][4];
    #pragma unroll
    for (int i = 0; i < 2; i++)
        #pragma unroll
        for (int j = 0; j < 8; j++)
            #pragma unroll
            for (int k = 0; k < 4; k++) acc[i][j][k] = 0.f;

    const int r_lane = (lane & 7) + ((lane >> 3) & 1) * 8;
    uint32_t aRow[2], aSw[2];
    #pragma unroll
    for (int mt = 0; mt < 2; mt++){
        int m_loc = wm * 32 + mt * 16 + r_lane;
        aRow[mt] = (uint32_t)(m_loc * 128);
        aSw[mt]  = (uint32_t)(m_loc & 7);
    }
    const uint32_t aCk = (lane >> 4) & 1;
    uint32_t bRow[4], bSw[4];
    {
        int n_base = wn * 64 + ((lane >> 4) & 1) * 8 + (lane & 7);
        #pragma unroll
        for (int g = 0; g < 4; g++){
            int n_loc = n_base + g * 16;
            bRow[g] = (uint32_t)(n_loc * 128);
            bSw[g]  = (uint32_t)(n_loc & 7);
        }
    }
    const uint32_t bCk = (lane >> 3) & 1;

    const int C = Kdim >> 6;

    auto load_stage = [&](int c){
        const uint32_t sb = tiles + (c % 3) * STAGE_B;
        const int k0 = c << 6;
        #pragma unroll
        for (int i = 0; i < 4; i++){
            int idx = tid + i * 256;
            int row = idx >> 3, ch = idx & 7;
            uint32_t so = (uint32_t)(row * 128 + ((ch ^ (row & 7)) << 4));
            CP16(sb + so, A + (size_t)(m0 + row) * lda + k0 + ch * 8);
        }
        #pragma unroll
        for (int i = 0; i < 4; i++){
            int idx = tid + i * 256;
            int row = idx >> 3, ch = idx & 7;
            uint32_t so = (uint32_t)(row * 128 + ((ch ^ (row & 7)) << 4));
            CP16(sb + 16384 + so, B + (size_t)(n0 + row) * ldb + k0 + ch * 8);
        }
    };

    load_stage(0); CP_COMMIT();
    load_stage(1); CP_COMMIT();

    for (int c = 0; c < C; c++){
        if (c < C - 1) CP_WAIT1(); else CP_WAIT0();
        __syncthreads();
        if (c + 2 < C){ load_stage(c + 2); CP_COMMIT(); }

        const uint32_t sb = tiles + (c % 3) * STAGE_B;
        #pragma unroll
        for (int ks = 0; ks < 4; ks++){
            uint32_t ah[2][4];
            #pragma unroll
            for (int mt = 0; mt < 2; mt++){
                uint32_t off = aRow[mt] + ((((uint32_t)(2 * ks) + aCk) ^ aSw[mt]) << 4);
                ldm4(ah[mt], sb + off);
            }
            uint32_t bb[8][2];
            #pragma unroll
            for (int g = 0; g < 4; g++){
                uint32_t off = bRow[g] + ((((uint32_t)(2 * ks) + bCk) ^ bSw[g]) << 4);
                uint32_t q[4];
                ldm4(q, sb + 16384 + off);
                bb[2*g][0]=q[0]; bb[2*g][1]=q[1]; bb[2*g+1][0]=q[2]; bb[2*g+1][1]=q[3];
            }
            #pragma unroll
            for (int mt = 0; mt < 2; mt++)
                #pragma unroll
                for (int nf = 0; nf < 8; nf++)
                    mma_f16(acc[mt][nf], ah[mt], bb[nf]);
        }
    }

    const int er = lane >> 2, ec = (lane & 3) * 2;
    if (EPI == 3){
        float* rs = reinterpret_cast<float*>(dynsm + (tiles - smbase));
        float rowp[2][2] = {};
        #pragma unroll
        for (int mt = 0; mt < 2; mt++)
            #pragma unroll
            for (int nf = 0; nf < 8; nf++){
                const int n = n0 + wn * 64 + nf * 8 + ec;
                #pragma unroll
                for (int rr = 0; rr < 2; rr++){
                    const int m = m0 + wm * 32 + mt * 16 + er + rr * 8;
                    float e0 = __expf(acc[mt][nf][rr*2]   * scale);
                    float e1 = __expf(acc[mt][nf][rr*2+1] * scale);
                    __half2 hp = __floats2half2_rn(e0, e1);
                    *reinterpret_cast<uint32_t*>(C16 + (size_t)m * ldc + n) = *reinterpret_cast<uint32_t*>(&hp);
                    rowp[mt][rr] += e0 + e1;
                }
            }
        __syncthreads();
        #pragma unroll
        for (int mt = 0; mt < 2; mt++)
            #pragma unroll
            for (int rr = 0; rr < 2; rr++){
                float v = rowp[mt][rr];
                v += __shfl_xor_sync(0xffffffffu, v, 1);
                v += __shfl_xor_sync(0xffffffffu, v, 2);
                if ((lane & 3) == 0){
                    int row = wm * 32 + mt * 16 + rr * 8 + er;
                    rs[wn * 128 + row] = v;
                }
            }
        __syncthreads();
        if (tid < 128)
            esBase[(size_t)(m0 + tid) * NBLK + nblk] = rs[tid] + rs[128 + tid];
        return;
    }
    if (EPI == 4){
        float invr[2][2];
        #pragma unroll
        for (int mt = 0; mt < 2; mt++)
            #pragma unroll
            for (int rr = 0; rr < 2; rr++){
                const int m = m0 + wm * 32 + mt * 16 + er + rr * 8;
                const float4* p = reinterpret_cast<const float4*>(esBase + (size_t)m * NBLK);
                float s = 0.f;
                #pragma unroll
                for (int i = 0; i < NBLK/4; i++){
                    float4 v = p[i];
                    s += (v.x + v.y) + (v.z + v.w);
                }
                invr[mt][rr] = 1.f / s;
            }
        #pragma unroll
        for (int mt = 0; mt < 2; mt++)
            #pragma unroll
            for (int nf = 0; nf < 8; nf++){
                const int n = n0 + wn * 64 + nf * 8 + ec;
                #pragma unroll
                for (int rr = 0; rr < 2; rr++){
                    const int m = m0 + wm * 32 + mt * 16 + er + rr * 8;
                    __half2 hp = __floats2half2_rn(acc[mt][nf][rr*2]   * invr[mt][rr],
                                                   acc[mt][nf][rr*2+1] * invr[mt][rr]);
                    *reinterpret_cast<uint32_t*>(C16 + (size_t)m * ldc + n) = *reinterpret_cast<uint32_t*>(&hp);
                }
            }
        return;
    }
    if (EPI == 2){
        #pragma unroll
        for (int mt = 0; mt < 2; mt++)
            #pragma unroll
            for (int nf = 0; nf < 8; nf++){
                const int n = n0 + wn * 64 + nf * 8 + ec;
                #pragma unroll
                for (int rr = 0; rr < 2; rr++){
                    const int m = m0 + wm * 32 + mt * 16 + er + rr * 8;
                    size_t off = (size_t)m * ldc + n;
                    float2 rv = *reinterpret_cast<const float2*>(resid + off);
                    float2 bv = *reinterpret_cast<const float2*>(bias + n);
                    float2 o;
                    o.x = acc[mt][nf][rr*2]   + rv.x + bv.x;
                    o.y = acc[mt][nf][rr*2+1] + rv.y + bv.y;
                    *reinterpret_cast<float2*>(Cf + off) = o;
                }
            }
        return;
    }
    // EPI 0
    #pragma unroll
    for (int mt = 0; mt < 2; mt++)
        #pragma unroll
        for (int nf = 0; nf < 8; nf++){
            const int n = n0 + wn * 64 + nf * 8 + ec;
            #pragma unroll
            for (int rr = 0; rr < 2; rr++){
                const int m = m0 + wm * 32 + mt * 16 + er + rr * 8;
                __half2 hp = __floats2half2_rn(acc[mt][nf][rr*2], acc[mt][nf][rr*2+1]);
                *reinterpret_cast<uint32_t*>(C16 + (size_t)m * ldc + n) = *reinterpret_cast<uint32_t*>(&hp);
            }
        }
}

// ---------------- dataflow helpers ----------------
__device__ __forceinline__ void gate(int idx, int target){
    if (threadIdx.x == 0){
        while (atomicAdd(&g_cnt[idx], 0) < target) __nanosleep(100);
    }
    __syncthreads();
}
__device__ __forceinline__ void signal(int idx){
    __syncthreads();
    if (threadIdx.x == 0){ __threadfence(); atomicAdd(&g_cnt[idx], 1); }
}

// ---------------- megakernel: qproj | gemmE | gemmZ | gemmOut via counters ----------------
// grid = 512 + 4096 + 512 + 512 = 5632 blocks (1D). Blocks only wait on lower ids.
__global__ void __launch_bounds__(256, 2)
mega(const __half* __restrict__ x16, const __half* __restrict__ y16,
     const __half* __restrict__ yT16,
     const __half* __restrict__ WqkT, const __half* __restrict__ Wvo,
     __half* __restrict__ Q16, __half* __restrict__ E16, float* __restrict__ Esum,
     float* __restrict__ out, const float* __restrict__ x, const float* __restrict__ bo,
     float scale)
{
    extern __shared__ char dynsm[];
    const int id = blockIdx.x;
    if (id < 512){
        // qproj: Q' = x @ Wqk ; global m-block gm = id>>2
        const int gm = id >> 2;
        gemm_core<0>(x16, EMBED, WqkT, EMBED, EMBED,
                     gm * 128, (id & 3) * 128,
                     Q16, EMBED, nullptr, nullptr, nullptr, 1.0f, nullptr, 0, dynsm);
        signal(gm);                                  // qcnt[gm] target 4
    } else if (id < 4608){
        const int e = id - 512;
        const int b = e >> 9, r = e & 511, by = r >> 5, bx = r & 31;
        gate(b * 16 + by, 4);                        // wait Q' rows
        gemm_core<3>(Q16 + (size_t)b * QLEN * EMBED, EMBED,
                     y16 + (size_t)b * KLEN * EMBED, EMBED, EMBED,
                     by * 128, bx * 128,
                     E16 + (size_t)b * QLEN * KLEN, KLEN,
                     nullptr, nullptr, nullptr, scale,
                     Esum + (size_t)b * QLEN * NBLK, bx, dynsm);
        signal(128 + b * 16 + by);                   // ecnt target 32
    } else if (id < 5120){
        const int z = id - 4608;
        const int b = z >> 6, r = z & 63, my = r >> 2, nx = r & 3;
        gate(128 + b * 16 + my, 32);                 // wait E rows + Esum
        gemm_core<4>(E16 + (size_t)b * QLEN * KLEN, KLEN,
                     yT16 + (size_t)b * EMBED * KLEN, KLEN, KLEN,
                     my * 128, nx * 128,
                     Q16 + (size_t)b * QLEN * EMBED, EMBED,   // Z reuses Q16
                     nullptr, nullptr, nullptr, 1.0f,
                     Esum + (size_t)b * QLEN * NBLK, 0, dynsm);
        signal(256 + b * 16 + my);                   // zcnt target 4
    } else {
        const int o = id - 5120;
        const int gm = o >> 2;
        gate(256 + gm, 4);                           // wait Z rows
        gemm_core<2>(Q16, EMBED, Wvo, EMBED, EMBED,
                     gm * 128, (o & 3) * 128,
                     nullptr, EMBED, out, x, bo, 1.0f, nullptr, 0, dynsm);
    }
}

// ---------------- prelude kernels ----------------
__global__ void __launch_bounds__(256, 2)
gemmW2(const __half* __restrict__ T1, const __half* __restrict__ T2,
       const __half* __restrict__ T3, const __half* __restrict__ Wo,
       __half* __restrict__ WqkT, __half* __restrict__ Wvo)
{
    extern __shared__ char dynsm[];
    const __half* A; const __half* B; __half* D;
    if (blockIdx.z == 0){ A = T2; B = T1; D = WqkT; }
    else                { A = Wo; B = T3; D = Wvo;  }
    gemm_core<0>(A, EMBED, B, EMBED, EMBED,
                 blockIdx.y * 128, blockIdx.x * 128,
                 D, EMBED, nullptr, nullptr, nullptr, 1.0f, nullptr, 0, dynsm);
}

__global__ void __launch_bounds__(256, 1)
trW3(const __half* __restrict__ Wq, const __half* __restrict__ Wk,
     const __half* __restrict__ Wv,
     __half* __restrict__ T1, __half* __restrict__ T2, __half* __restrict__ T3)
{
    __shared__ __half s[32][33];
    const __half* src = (blockIdx.z == 0) ? Wq : (blockIdx.z == 1) ? Wk : Wv;
    __half*       dst = (blockIdx.z == 0) ? T1 : (blockIdx.z == 1) ? T2 : T3;
    const int x0 = blockIdx.x * 32, y0 = blockIdx.y * 32;
    const int tx = threadIdx.x & 31, ty = threadIdx.x >> 5;
    #pragma unroll
    for (int i = ty; i < 32; i += 8)
        s[i][tx] = src[(size_t)(y0 + i) * EMBED + x0 + tx];
    __syncthreads();
    #pragma unroll
    for (int i = ty; i < 32; i += 8)
        dst[(size_t)(x0 + i) * EMBED + y0 + tx] = s[tx][i];
}

#define NXE (MQ*EMBED)
__global__ void __launch_bounds__(256, 1)
cvtXW(const float* __restrict__ x,
      const float* __restrict__ w0, const float* __restrict__ w1,
      const float* __restrict__ w2, const float* __restrict__ w3,
      __half* __restrict__ x16, __half* __restrict__ W16)
{
    int e = (blockIdx.x * 256 + threadIdx.x) * 4;
    const float* src; __half* dst;
    if (e < NXE){ src = x + e; dst = x16 + e; }
    else {
        int o = e - NXE;
        int w = o / NW, r = o % NW;
        src = (w == 0 ? w0 : w == 1 ? w1 : w == 2 ? w2 : w3) + r;
        dst = W16 + (size_t)w * NW + r;
    }
    float4 v = *reinterpret_cast<const float4*>(src);
    __half2 a = __floats2half2_rn(v.x, v.y);
    __half2 b = __floats2half2_rn(v.z, v.w);
    uint2 o;
    o.x = *reinterpret_cast<uint32_t*>(&a);
    o.y = *reinterpret_cast<uint32_t*>(&b);
    *reinterpret_cast<uint2*>(dst) = o;
}

__global__ void __launch_bounds__(256, 1)
cvtY(const float* __restrict__ y, __half* __restrict__ y16, __half* __restrict__ yT16)
{
    __shared__ __half s[32][33];
    const int b = blockIdx.z, kk0 = blockIdx.x * 32, d0 = blockIdx.y * 32;
    const int tx = threadIdx.x & 31, ty = threadIdx.x >> 5;
    const float* src = y + (size_t)b * KLEN * EMBED;
    __half* d1 = y16 + (size_t)b * KLEN * EMBED;
    #pragma unroll
    for (int i = ty; i < 32; i += 8){
        __half h = __float2half(src[(size_t)(kk0 + i) * EMBED + d0 + tx]);
        d1[(size_t)(kk0 + i) * EMBED + d0 + tx] = h;
        s[i][tx] = h;
    }
    __syncthreads();
    __half* d2 = yT16 + (size_t)b * EMBED * KLEN;
    #pragma unroll
    for (int i = ty; i < 32; i += 8)
        d2[(size_t)(d0 + i) * KLEN + kk0 + tx] = s[tx][i];
}

// ---------------- launch ----------------
extern "C" void kernel_launch(void* const* d_in, const int* in_sizes, int n_in,
                              void* d_out, int out_size)
{
    const float* x  = (const float*)d_in[0];
    const float* y  = (const float*)d_in[1];
    const float* Wq = (const float*)d_in[2];
    const float* Wk = (const float*)d_in[3];
    const float* Wv = (const float*)d_in[4];
    const float* Wo = (const float*)d_in[5];
    const float* bo = (const float*)d_in[6];
    float* out = (float*)d_out;

    __half *x16,*y16,*yT16,*W16,*T1,*T2,*T3,*Q16,*E16;
    float *Esum;
    int *cnt;
    cudaGetSymbolAddress((void**)&x16,  g_x16);
    cudaGetSymbolAddress((void**)&y16,  g_y16);
    cudaGetSymbolAddress((void**)&yT16, g_yT16);
    cudaGetSymbolAddress((void**)&W16,  g_W16);
    cudaGetSymbolAddress((void**)&T1,   g_T1);
    cudaGetSymbolAddress((void**)&T2,   g_T2);
    cudaGetSymbolAddress((void**)&T3,   g_T3);
    cudaGetSymbolAddress((void**)&Q16,  g_Q16);
    cudaGetSymbolAddress((void**)&E16,  g_E16);
    cudaGetSymbolAddress((void**)&Esum, g_Esum);
    cudaGetSymbolAddress((void**)&cnt,  g_cnt);
    __half* Wq16 = W16;                       // -> WqkT
    __half* Wk16 = W16 + (size_t)NW;
    __half* Wv16 = W16 + (size_t)2 * NW;      // -> Wvo
    __half* Wo16 = W16 + (size_t)3 * NW;
    cudaFuncSetAttribute(mega,   cudaFuncAttributeMaxDynamicSharedMemorySize, GSMEM);
    cudaFuncSetAttribute(gemmW2, cudaFuncAttributeMaxDynamicSharedMemorySize, GSMEM);

    const float sc = 1.0f / sqrtf((float)EMBED);

    cudaMemsetAsync(cnt, 0, 384 * sizeof(int));
    cvtXW<<<(NXE + 4*NW)/1024, 256>>>(x, Wq, Wk, Wv, Wo, x16, W16);
    cvtY<<<dim3(KLEN/32, EMBED/32, NBATCH), 256>>>(y, y16, yT16);
    trW3<<<dim3(16,16,3), 256>>>(Wq16, Wk16, Wv16, T1, T2, T3);
    gemmW2<<<dim3(4,4,2), 256, GSMEM>>>(T1, T2, T3, Wo16, Wq16, Wv16);
    // fused qproj -> gemmE -> gemmZ -> gemmOut with counter dataflow
    mega<<<5632, 256, GSMEM>>>(x16, y16, yT16, Wq16, Wv16,
                               Q16, E16, Esum, out, x, bo, sc);
}